// round 6
// baseline (speedup 1.0000x reference)
#include <cuda_runtime.h>
#include <cuda_fp16.h>
#include <math.h>

#define N_ATOMS 50000
#define N_EDGES 400000
#define N_MOLS  500
#define HID     128
#define NRBF    20
#define NLAYERS 4
#define NV      (N_ATOMS * HID)

#define TAB_D   8192
#define TAB_MAX 12.0f
#define RBF_STEP (5.0f / (float)(NRBF - 1))

typedef unsigned long long ull;

// ---------------- device scratch ----------------
__device__ float g_s[NV];        // parity 0 buffer
__device__ float g_s2[NV];       // parity 1 buffer
__device__ float g_v[3 * NV];    // planar [3][N][HID], parity 0
__device__ float g_v2[3 * NV];   // parity 1
__device__ float g_ms[NV];
__device__ float g_vn[NV];       // ||m_v||
__device__ float g_mv[3 * NV];
__device__ __half2 g_htabh[NLAYERS * TAB_D * 3 * HID];  // (.x=h(i), .y=h(i+1))
__device__ float g_hmol[N_MOLS * HID];
__device__ float g_cnt[N_MOLS];

// CSR scratch
__device__ int   g_deg[N_ATOMS];
__device__ int   g_rowptr[N_ATOMS + 1];
__device__ int   g_cursor[N_ATOMS];
__device__ int   g_bsum[128];
__device__ int   g_ecol[N_EDGES];
__device__ float4 g_egeo[N_EDGES];   // (dirx, diry, dirz, dist)

__device__ __forceinline__ float silu_f(float x) { return x / (1.0f + expf(-x)); }

__device__ __forceinline__ ull pack2(float lo, float hi) {
    ull r;
    asm("mov.b64 %0, {%1, %2};" : "=l"(r) : "f"(lo), "f"(hi));
    return r;
}
__device__ __forceinline__ void unpack2(ull v, float& lo, float& hi) {
    asm("mov.b64 {%0, %1}, %2;" : "=f"(lo), "=f"(hi) : "l"(v));
}
#define FMA_F32X2(acc, a, b) \
    asm("fma.rn.f32x2 %0, %1, %2, %0;" : "+l"(acc) : "l"(a), "l"(b))

// ---------------- init ----------------
__global__ void init_kernel(const int* __restrict__ z, const float* __restrict__ emb) {
    int idx = blockIdx.x * blockDim.x + threadIdx.x;
    if (idx < N_ATOMS) g_deg[idx] = 0;
    if (idx >= NV) return;
    int n = idx >> 7;
    int j = idx & 127;
    g_s[idx] = emb[z[n] * HID + j];
    g_v[idx] = 0.0f; g_v[NV + idx] = 0.0f; g_v[2 * NV + idx] = 0.0f;
}

// ---------------- CSR build ----------------
__global__ void hist_kernel(const int* __restrict__ ei) {
    int e = blockIdx.x * blockDim.x + threadIdx.x;
    if (e >= N_EDGES) return;
    atomicAdd(&g_deg[ei[e]], 1);
}

#define SCAN_B 512
__global__ void scan1_kernel() {
    __shared__ int s[SCAN_B];
    int t = threadIdx.x;
    int i = blockIdx.x * SCAN_B + t;
    int v = (i < N_ATOMS) ? g_deg[i] : 0;
    s[t] = v;
    __syncthreads();
    for (int off = 1; off < SCAN_B; off <<= 1) {
        int add = (t >= off) ? s[t - off] : 0;
        __syncthreads();
        s[t] += add;
        __syncthreads();
    }
    if (i < N_ATOMS) g_rowptr[i] = s[t] - v;
    if (t == SCAN_B - 1) g_bsum[blockIdx.x] = s[t];
}

__global__ void scan2_kernel(int nblocks) {
    if (threadIdx.x == 0) {
        int run = 0;
        for (int b = 0; b < nblocks; b++) {
            int t = g_bsum[b];
            g_bsum[b] = run;
            run += t;
        }
    }
}

__global__ void scan3_kernel() {
    int i = blockIdx.x * blockDim.x + threadIdx.x;
    if (i < N_ATOMS) {
        int rp = g_rowptr[i] + g_bsum[i >> 9];
        g_rowptr[i] = rp;
        g_cursor[i] = rp;
    }
    if (i == 0) g_rowptr[N_ATOMS] = N_EDGES;
}

__global__ void scatter_kernel(const int* __restrict__ ei, const float* __restrict__ pos) {
    int e = blockIdx.x * blockDim.x + threadIdx.x;
    if (e >= N_EDGES) return;
    int r = ei[e];
    int c = ei[N_EDGES + e];
    float dx = pos[c * 3 + 0] - pos[r * 3 + 0];
    float dy = pos[c * 3 + 1] - pos[r * 3 + 1];
    float dz = pos[c * 3 + 2] - pos[r * 3 + 2];
    float dist = sqrtf(dx * dx + dy * dy + dz * dz);
    float inv = 1.0f / (dist + 1e-8f);
    int p = atomicAdd(&g_cursor[r], 1);
    g_ecol[p] = c;
    g_egeo[p] = make_float4(dx * inv, dy * inv, dz * inv, dist);
}

// ---------------- filter table build (fp32 math, half2 endpoint store) ----------------
#define TAB_SMEM_FLOATS 20736

extern "C" __global__ void __launch_bounds__(512, 1)
table_kernel(const float* __restrict__ fW1, const float* __restrict__ fb1,
             const float* __restrict__ fW2, const float* __restrict__ fb2) {
    extern __shared__ float sm[];
    float* hid = sm;                 // [64][132]
    float* rbf_s = sm + 8448;        // [64][20]
    float* w1_s = sm + 9728;         // [20][128]
    float* w2_s = sm + 8448;         // [32][384] (stage2, overlaps)

    const int tid = threadIdx.x;
    const int layer = blockIdx.y;
    const int g0 = blockIdx.x * 64;
    const float* W1 = fW1 + layer * NRBF * HID;
    const float* b1 = fb1 + layer * HID;
    const float* W2 = fW2 + layer * HID * 3 * HID;
    const float* b2 = fb2 + layer * 3 * HID;
    const float DELTA = TAB_MAX / (float)(TAB_D - 1);

    for (int idx = tid; idx < 64 * NRBF; idx += 512) {
        int e = idx / NRBF, k = idx % NRBF;
        float d = (float)(g0 + e) * DELTA - RBF_STEP * (float)k;
        rbf_s[idx] = expf(-d * d);
    }
    for (int idx = tid; idx < NRBF * HID; idx += 512) w1_s[idx] = W1[idx];
    __syncthreads();

    const int jg = tid & 31;
    const int eg = tid >> 5;
    const int j0 = jg * 4;
    const int el0 = eg * 4;

    float hacc[4][4];
#pragma unroll
    for (int a = 0; a < 4; a++)
#pragma unroll
        for (int b = 0; b < 4; b++) hacc[a][b] = b1[j0 + b];
#pragma unroll
    for (int k = 0; k < NRBF; k++) {
        float r[4];
#pragma unroll
        for (int a = 0; a < 4; a++) r[a] = rbf_s[(el0 + a) * NRBF + k];
        float4 w = *(const float4*)&w1_s[k * HID + j0];
        float wv[4] = {w.x, w.y, w.z, w.w};
#pragma unroll
        for (int a = 0; a < 4; a++)
#pragma unroll
            for (int b = 0; b < 4; b++) hacc[a][b] += r[a] * wv[b];
    }
#pragma unroll
    for (int a = 0; a < 4; a++)
#pragma unroll
        for (int b = 0; b < 4; b++) hid[(el0 + a) * 132 + j0 + b] = silu_f(hacc[a][b]);
    __syncthreads();

    float a_ss[4][4], a_vv[4][4], a_sv[4][4];
#pragma unroll
    for (int a = 0; a < 4; a++)
#pragma unroll
        for (int b = 0; b < 4; b++) { a_ss[a][b] = 0.f; a_vv[a][b] = 0.f; a_sv[a][b] = 0.f; }

    for (int kc = 0; kc < HID; kc += 32) {
        __syncthreads();
        for (int idx = tid; idx < 32 * 384; idx += 512) w2_s[idx] = W2[kc * 384 + idx];
        __syncthreads();
#pragma unroll 8
        for (int kk = 0; kk < 32; kk++) {
            float h[4];
#pragma unroll
            for (int a = 0; a < 4; a++) h[a] = hid[(el0 + a) * 132 + kc + kk];
            float4 wss = *(const float4*)&w2_s[kk * 384 + j0];
            float4 wvv = *(const float4*)&w2_s[kk * 384 + 128 + j0];
            float4 wsv = *(const float4*)&w2_s[kk * 384 + 256 + j0];
            float ss[4] = {wss.x, wss.y, wss.z, wss.w};
            float vv[4] = {wvv.x, wvv.y, wvv.z, wvv.w};
            float sv[4] = {wsv.x, wsv.y, wsv.z, wsv.w};
#pragma unroll
            for (int a = 0; a < 4; a++)
#pragma unroll
                for (int b = 0; b < 4; b++) {
                    a_ss[a][b] += h[a] * ss[b];
                    a_vv[a][b] += h[a] * vv[b];
                    a_sv[a][b] += h[a] * sv[b];
                }
        }
    }

#pragma unroll
    for (int a = 0; a < 4; a++) {
        int gi = g0 + el0 + a;
        __half* Tx = (__half*)(g_htabh + ((size_t)layer * TAB_D + gi) * 384);
        __half* Ty = (__half*)(g_htabh + ((size_t)layer * TAB_D + gi - 1) * 384);
#pragma unroll
        for (int b = 0; b < 4; b++) {
            float hss = a_ss[a][b] + b2[j0 + b];
            float hvv = a_vv[a][b] + b2[128 + j0 + b];
            float hsv = a_sv[a][b] + b2[256 + j0 + b];
            Tx[(j0 + b) * 2]         = __float2half(hss);
            Tx[(128 + j0 + b) * 2]   = __float2half(hvv);
            Tx[(256 + j0 + b) * 2]   = __float2half(hsv);
            if (gi > 0) {
                Ty[(j0 + b) * 2 + 1]       = __float2half(hss);
                Ty[(128 + j0 + b) * 2 + 1] = __float2half(hvv);
                Ty[(256 + j0 + b) * 2 + 1] = __float2half(hsv);
            }
        }
    }
}

// ---------------- fused layer kernel: msg (phase A) + node MLP (phase B) ----------------
// 64 nodes/CTA, 256 threads, 2 CTAs/SM. Double-buffered s/v (parity).
// Phase A: 8 warps x 8 CSR rows -> g_ms, g_vn, g_mv (CTA-exclusive rows).
// Phase B: register-blocked MLP (f32x2 FMA), reads phase-A results after __syncthreads.
#define NT 64
#define XS_STRIDE 76
#define NODE_SMEM_FLOATS 22784

extern "C" __global__ void __launch_bounds__(256, 2)
layer_kernel(int layer,
             const float* __restrict__ uW1, const float* __restrict__ ub1,
             const float* __restrict__ uW2, const float* __restrict__ ub2) {
    extern __shared__ float sm[];
    float* xs_t = sm;              // [64 k][76]
    float* wc   = sm + 4864;       // [64 k][128]
    float* ts_t = sm + 13056;      // [128 k][76]

    const int tid = threadIdx.x;
    const int lane = tid & 31;
    const int wid = tid >> 5;
    const int n0 = blockIdx.x * NT;

    const float* s_in  = (layer & 1) ? g_s2 : g_s;
    float*       s_out = (layer & 1) ? g_s  : g_s2;
    const float* v_in  = (layer & 1) ? g_v2 : g_v;
    float*       v_out = (layer & 1) ? g_v  : g_v2;

    const float* W1 = uW1 + layer * 384 * HID;
    const float* b1 = ub1 + layer * HID;
    const float* W2 = uW2 + layer * HID * 384;
    const float* b2 = ub2 + layer * 384;

    // prefetch W1 chunk 0 — LDG latency absorbed by phase A
    float4 wreg[8];
#pragma unroll
    for (int q = 0; q < 8; q++) {
        int idx = q * 256 + tid;
        int k = idx >> 5, c4 = idx & 31;
        wreg[q] = *(const float4*)&W1[k * HID + c4 * 4];
    }

    // ================= Phase A: messages for rows n0 .. n0+63 =================
    {
        const float INV_DELTA = (float)(TAB_D - 1) / TAB_MAX;
        const __half2* Tl = g_htabh + (size_t)layer * TAB_D * 384;
        const bool hasv = (layer != 0);

        for (int rl = 0; rl < 8; rl++) {
            int r = n0 + wid * 8 + rl;
            if (r >= N_ATOMS) break;
            int beg = g_rowptr[r];
            int end = g_rowptr[r + 1];

            float accS[4] = {0.f, 0.f, 0.f, 0.f};
            float accV[12];
#pragma unroll
            for (int q = 0; q < 12; q++) accV[q] = 0.f;

            for (int p = beg; p < end; p++) {
                int col = g_ecol[p];
                float4 geo = g_egeo[p];
                float u = geo.w * INV_DELTA;
                int i0 = (int)u;
                if (i0 > TAB_D - 2) i0 = TAB_D - 2;
                float f = u - (float)i0;
                const __half2* T = Tl + (size_t)i0 * 384;

#pragma unroll
                for (int b = 0; b < 4; b++) {
                    int j = lane + 32 * b;
                    float2 pss = __half22float2(__ldcg(&T[j]));
                    float2 pvv = __half22float2(__ldcg(&T[128 + j]));
                    float2 psv = __half22float2(__ldcg(&T[256 + j]));
                    float hss = pss.x + f * (pss.y - pss.x);
                    float hvv = pvv.x + f * (pvv.y - pvv.x);
                    float hsv = psv.x + f * (psv.y - psv.x);
                    float sc = __ldcg(&s_in[col * HID + j]);
                    accS[b] += hss * sc;
                    float cc = hsv * sc;
                    if (hasv) {
                        accV[b]     += hvv * __ldcg(&v_in[col * HID + j])          + cc * geo.x;
                        accV[4 + b] += hvv * __ldcg(&v_in[NV + col * HID + j])     + cc * geo.y;
                        accV[8 + b] += hvv * __ldcg(&v_in[2 * NV + col * HID + j]) + cc * geo.z;
                    } else {
                        accV[b]     += cc * geo.x;
                        accV[4 + b] += cc * geo.y;
                        accV[8 + b] += cc * geo.z;
                    }
                }
            }

#pragma unroll
            for (int b = 0; b < 4; b++) {
                int j = lane + 32 * b;
                g_ms[r * HID + j] = accS[b];
                float mx = accV[b], my = accV[4 + b], mz = accV[8 + b];
                g_vn[r * HID + j] = sqrtf(mx * mx + my * my + mz * mz);
                g_mv[r * HID + j] = mx;
                g_mv[NV + r * HID + j] = my;
                g_mv[2 * NV + r * HID + j] = mz;
            }
        }
    }
    // phase A results visible to whole CTA after the first __syncthreads below

    // ================= Phase B: node MLP =================
    const int og = tid & 31;
    const int ng = tid >> 5;
    const int j0 = og * 4;
    const int nl0 = ng * 8;

    float4 b1v = *(const float4*)&b1[j0];
    ull accP[4][4];
    {
        float bb[4] = {b1v.x, b1v.y, b1v.z, b1v.w};
#pragma unroll
        for (int ap = 0; ap < 4; ap++)
#pragma unroll
            for (int b = 0; b < 4; b++) accP[ap][b] = pack2(bb[b], bb[b]);
    }

    for (int kc = 0; kc < 384; kc += 64) {
        __syncthreads();
#pragma unroll
        for (int q = 0; q < 8; q++) {
            int idx = q * 256 + tid;
            int k = idx >> 5, c4 = idx & 31;
            *(float4*)&wc[k * 128 + c4 * 4] = wreg[q];
        }
        for (int idx = tid; idx < 64 * 64; idx += 256) {
            int node = idx >> 6, k = idx & 63;
            int gk = kc + k, gn = n0 + node;
            float val = 0.f;
            if (gn < N_ATOMS) {
                if (gk < 128)      val = s_in[gn * HID + gk];
                else if (gk < 256) val = g_ms[gn * HID + (gk - 128)];
                else               val = g_vn[gn * HID + (gk - 256)];
            }
            xs_t[k * XS_STRIDE + node] = val;
        }
        __syncthreads();
        if (kc + 64 < 384) {
#pragma unroll
            for (int q = 0; q < 8; q++) {
                int idx = q * 256 + tid;
                int k = idx >> 5, c4 = idx & 31;
                wreg[q] = *(const float4*)&W1[(kc + 64 + k) * HID + c4 * 4];
            }
        } else {
#pragma unroll
            for (int q = 0; q < 8; q++) {
                int idx = q * 256 + tid;
                int k = idx >> 5, c4 = idx & 31;
                wreg[q] = *(const float4*)&W2[k * 384 + c4 * 4];
            }
        }
#pragma unroll 4
        for (int kk = 0; kk < 64; kk++) {
            const ull* ax = (const ull*)&xs_t[kk * XS_STRIDE + nl0];
            ull a0 = ax[0], a1 = ax[1], a2 = ax[2], a3 = ax[3];
            float4 w = *(const float4*)&wc[kk * 128 + j0];
            ull w0 = pack2(w.x, w.x), w1 = pack2(w.y, w.y);
            ull w2 = pack2(w.z, w.z), w3 = pack2(w.w, w.w);
            FMA_F32X2(accP[0][0], a0, w0); FMA_F32X2(accP[1][0], a1, w0);
            FMA_F32X2(accP[2][0], a2, w0); FMA_F32X2(accP[3][0], a3, w0);
            FMA_F32X2(accP[0][1], a0, w1); FMA_F32X2(accP[1][1], a1, w1);
            FMA_F32X2(accP[2][1], a2, w1); FMA_F32X2(accP[3][1], a3, w1);
            FMA_F32X2(accP[0][2], a0, w2); FMA_F32X2(accP[1][2], a1, w2);
            FMA_F32X2(accP[2][2], a2, w2); FMA_F32X2(accP[3][2], a3, w2);
            FMA_F32X2(accP[0][3], a0, w3); FMA_F32X2(accP[1][3], a1, w3);
            FMA_F32X2(accP[2][3], a2, w3); FMA_F32X2(accP[3][3], a3, w3);
        }
    }
#pragma unroll
    for (int ap = 0; ap < 4; ap++)
#pragma unroll
        for (int b = 0; b < 4; b++) {
            float lo, hi;
            unpack2(accP[ap][b], lo, hi);
            ts_t[(j0 + b) * XS_STRIDE + nl0 + 2 * ap] = silu_f(lo);
            ts_t[(j0 + b) * XS_STRIDE + nl0 + 2 * ap + 1] = silu_f(hi);
        }

    ull u2P[4][4];
    for (int c = 0; c < 6; c++) {
        int jb = c >> 1;
        int kc2 = (c & 1) * 64;
        if (kc2 == 0) {
#pragma unroll
            for (int ap = 0; ap < 4; ap++)
#pragma unroll
                for (int b = 0; b < 4; b++) u2P[ap][b] = 0ull;
        }
        __syncthreads();
#pragma unroll
        for (int q = 0; q < 8; q++) {
            int idx = q * 256 + tid;
            int k = idx >> 5, c4 = idx & 31;
            *(float4*)&wc[k * 128 + c4 * 4] = wreg[q];
        }
        __syncthreads();
        if (c < 5) {
            int cn = c + 1;
            int jbn = cn >> 1;
            int kc2n = (cn & 1) * 64;
#pragma unroll
            for (int q = 0; q < 8; q++) {
                int idx = q * 256 + tid;
                int k = idx >> 5, c4 = idx & 31;
                wreg[q] = *(const float4*)&W2[(kc2n + k) * 384 + jbn * 128 + c4 * 4];
            }
        }
#pragma unroll 4
        for (int kk = 0; kk < 64; kk++) {
            const ull* ax = (const ull*)&ts_t[(kc2 + kk) * XS_STRIDE + nl0];
            ull a0 = ax[0], a1 = ax[1], a2 = ax[2], a3 = ax[3];
            float4 w = *(const float4*)&wc[kk * 128 + j0];
            ull w0 = pack2(w.x, w.x), w1 = pack2(w.y, w.y);
            ull w2 = pack2(w.z, w.z), w3 = pack2(w.w, w.w);
            FMA_F32X2(u2P[0][0], a0, w0); FMA_F32X2(u2P[1][0], a1, w0);
            FMA_F32X2(u2P[2][0], a2, w0); FMA_F32X2(u2P[3][0], a3, w0);
            FMA_F32X2(u2P[0][1], a0, w1); FMA_F32X2(u2P[1][1], a1, w1);
            FMA_F32X2(u2P[2][1], a2, w1); FMA_F32X2(u2P[3][1], a3, w1);
            FMA_F32X2(u2P[0][2], a0, w2); FMA_F32X2(u2P[1][2], a1, w2);
            FMA_F32X2(u2P[2][2], a2, w2); FMA_F32X2(u2P[3][2], a3, w2);
            FMA_F32X2(u2P[0][3], a0, w3); FMA_F32X2(u2P[1][3], a1, w3);
            FMA_F32X2(u2P[2][3], a2, w3); FMA_F32X2(u2P[3][3], a3, w3);
        }

        if (kc2 == 64) {
            float u2[8][4];
#pragma unroll
            for (int ap = 0; ap < 4; ap++)
#pragma unroll
                for (int b = 0; b < 4; b++)
                    unpack2(u2P[ap][b], u2[2 * ap][b], u2[2 * ap + 1][b]);

            float4 b2v = *(const float4*)&b2[jb * 128 + j0];
            float bb[4] = {b2v.x, b2v.y, b2v.z, b2v.w};
#pragma unroll
            for (int a = 0; a < 8; a++) {
                int gn = n0 + nl0 + a;
                if (gn >= N_ATOMS) continue;
                if (jb == 0) {
#pragma unroll
                    for (int b = 0; b < 4; b++)
                        s_out[gn * HID + j0 + b] = s_in[gn * HID + j0 + b] + u2[a][b] + bb[b];
                } else if (jb == 1) {
#pragma unroll
                    for (int d = 0; d < 3; d++) {
                        const float4 vi = *(const float4*)&v_in[d * NV + gn * HID + j0];
                        float4 vv;
                        vv.x = vi.x * (u2[a][0] + bb[0]);
                        vv.y = vi.y * (u2[a][1] + bb[1]);
                        vv.z = vi.z * (u2[a][2] + bb[2]);
                        vv.w = vi.w * (u2[a][3] + bb[3]);
                        *(float4*)&v_out[d * NV + gn * HID + j0] = vv;
                    }
                } else {
#pragma unroll
                    for (int d = 0; d < 3; d++) {
                        float4* vp = (float4*)&v_out[d * NV + gn * HID + j0];
                        const float4* mp = (const float4*)&g_mv[d * NV + gn * HID + j0];
                        float4 vv = *vp;
                        float4 mv = *mp;
                        vv.x += (u2[a][0] + bb[0]) * mv.x;
                        vv.y += (u2[a][1] + bb[1]) * mv.y;
                        vv.z += (u2[a][2] + bb[2]) * mv.z;
                        vv.w += (u2[a][3] + bb[3]) * mv.w;
                        *vp = vv;
                    }
                }
            }
        }
    }
}

// ---------------- molecule pooling + heads ----------------
__global__ void pool_zero_kernel() {
    int idx = blockIdx.x * blockDim.x + threadIdx.x;
    if (idx < N_MOLS * HID) g_hmol[idx] = 0.f;
    if (idx < N_MOLS) g_cnt[idx] = 0.f;
}

__global__ void pool_acc_kernel(const int* __restrict__ batch) {
    int idx = blockIdx.x * blockDim.x + threadIdx.x;
    if (idx >= NV) return;
    int n = idx >> 7;
    int j = idx & 127;
    int m = batch[n];
    atomicAdd(&g_hmol[m * HID + j], g_s[idx]);   // final parity: g_s
    if (j == 0) atomicAdd(&g_cnt[m], 1.0f);
}

__global__ void head_kernel(const float* __restrict__ lW1, const float* __restrict__ lb1,
                            const float* __restrict__ lW2, const float* __restrict__ lb2,
                            const float* __restrict__ pW1, const float* __restrict__ pb1,
                            const float* __restrict__ pW2, const float* __restrict__ pb2,
                            float* __restrict__ out) {
    __shared__ float hm[HID];
    __shared__ float tt[HID];
    __shared__ float red[HID];
    int m = blockIdx.x;
    int j = threadIdx.x;
    float cnt = g_cnt[m];
    hm[j] = g_hmol[m * HID + j] / cnt;
    __syncthreads();

    float acc = lb1[j];
    for (int k = 0; k < HID; k++) acc += hm[k] * lW1[k * HID + j];
    tt[j] = silu_f(acc);
    __syncthreads();
    red[j] = tt[j] * lW2[j];
    __syncthreads();
    for (int s = 64; s > 0; s >>= 1) {
        if (j < s) red[j] += red[j + s];
        __syncthreads();
    }
    if (j == 0) out[m] = red[0] + lb2[0];
    __syncthreads();

    acc = pb1[j];
    for (int k = 0; k < HID; k++) acc += hm[k] * pW1[k * HID + j];
    tt[j] = silu_f(acc);
    __syncthreads();
    red[j] = tt[j] * pW2[j];
    __syncthreads();
    for (int s = 64; s > 0; s >>= 1) {
        if (j < s) red[j] += red[j + s];
        __syncthreads();
    }
    if (j == 0) {
        float x = red[0] + pb2[0];
        out[N_MOLS + m] = 1.0f / (1.0f + expf(-x));
    }
}

// ---------------- launch ----------------
extern "C" void kernel_launch(void* const* d_in, const int* in_sizes, int n_in,
                              void* d_out, int out_size) {
    const int* z = (const int*)d_in[0];
    const float* pos = (const float*)d_in[1];
    const int* ei = (const int*)d_in[2];
    const int* batch = (const int*)d_in[3];
    const float* emb = (const float*)d_in[4];
    const float* fW1 = (const float*)d_in[5];
    const float* fb1 = (const float*)d_in[6];
    const float* fW2 = (const float*)d_in[7];
    const float* fb2 = (const float*)d_in[8];
    const float* uW1 = (const float*)d_in[9];
    const float* ub1 = (const float*)d_in[10];
    const float* uW2 = (const float*)d_in[11];
    const float* ub2 = (const float*)d_in[12];
    const float* lW1 = (const float*)d_in[13];
    const float* lb1 = (const float*)d_in[14];
    const float* lW2 = (const float*)d_in[15];
    const float* lb2 = (const float*)d_in[16];
    const float* pW1 = (const float*)d_in[17];
    const float* pb1 = (const float*)d_in[18];
    const float* pW2 = (const float*)d_in[19];
    const float* pb2 = (const float*)d_in[20];
    float* out = (float*)d_out;

    cudaFuncSetAttribute(table_kernel, cudaFuncAttributeMaxDynamicSharedMemorySize,
                         TAB_SMEM_FLOATS * 4);
    cudaFuncSetAttribute(layer_kernel, cudaFuncAttributeMaxDynamicSharedMemorySize,
                         NODE_SMEM_FLOATS * 4);

    init_kernel<<<(NV + 255) / 256, 256>>>(z, emb);

    const int scan_blocks = (N_ATOMS + SCAN_B - 1) / SCAN_B;
    hist_kernel<<<(N_EDGES + 255) / 256, 256>>>(ei);
    scan1_kernel<<<scan_blocks, SCAN_B>>>();
    scan2_kernel<<<1, 32>>>(scan_blocks);
    scan3_kernel<<<(N_ATOMS + 255) / 256, 256>>>();
    scatter_kernel<<<(N_EDGES + 255) / 256, 256>>>(ei, pos);

    table_kernel<<<dim3(TAB_D / 64, NLAYERS), 512, TAB_SMEM_FLOATS * 4>>>(fW1, fb1, fW2, fb2);

    const int node_blocks = (N_ATOMS + NT - 1) / NT;
    for (int layer = 0; layer < NLAYERS; layer++) {
        layer_kernel<<<node_blocks, 256, NODE_SMEM_FLOATS * 4>>>(layer, uW1, ub1, uW2, ub2);
    }

    pool_zero_kernel<<<(N_MOLS * HID + 255) / 256, 256>>>();
    pool_acc_kernel<<<(NV + 255) / 256, 256>>>(batch);
    head_kernel<<<N_MOLS, HID>>>(lW1, lb1, lW2, lb2, pW1, pb1, pW2, pb2, out);
}

// round 7
// speedup vs baseline: 1.2912x; 1.2912x over previous
#include <cuda_runtime.h>
#include <cuda_fp16.h>
#include <math.h>

#define N_ATOMS 50000
#define N_EDGES 400000
#define N_MOLS  500
#define HID     128
#define NRBF    20
#define NLAYERS 4
#define NV      (N_ATOMS * HID)
#define NA64    (N_ATOMS * 64)

#define TAB_D   8192
#define TAB_MAX 12.0f
#define RBF_STEP (5.0f / (float)(NRBF - 1))

typedef unsigned long long ull;

// ---------------- device scratch ----------------
__device__ float g_s[NV];
__device__ float g_v[3 * NV];          // planar [3][N][HID] fp32 masters
__device__ __half2 g_sh2[NA64];        // packed (s[j], s[j+64]) at [n*64 + j], j<64
__device__ __half2 g_vh2[3 * NA64];    // same packing per plane
__device__ float g_ms[NV];
__device__ float g_vn[NV];             // ||m_v||
__device__ float g_mv[3 * NV];
__device__ __half2 g_htabh[NLAYERS * TAB_D * 3 * HID];  // (.x=h(i), .y=h(i+1))
__device__ float g_hmol[N_MOLS * HID];
__device__ float g_cnt[N_MOLS];

// CSR scratch
__device__ int   g_deg[N_ATOMS];
__device__ int   g_rowptr[N_ATOMS + 1];
__device__ int   g_cursor[N_ATOMS];
__device__ int   g_bsum[128];
__device__ int   g_ecol[N_EDGES];
__device__ float4 g_egeo[N_EDGES];     // (dirx, diry, dirz, dist)

__device__ __forceinline__ float silu_f(float x) { return x / (1.0f + expf(-x)); }

__device__ __forceinline__ ull pack2(float lo, float hi) {
    ull r;
    asm("mov.b64 %0, {%1, %2};" : "=l"(r) : "f"(lo), "f"(hi));
    return r;
}
__device__ __forceinline__ void unpack2(ull v, float& lo, float& hi) {
    asm("mov.b64 {%0, %1}, %2;" : "=f"(lo), "=f"(hi) : "l"(v));
}
#define FMA_F32X2(acc, a, b) \
    asm("fma.rn.f32x2 %0, %1, %2, %0;" : "+l"(acc) : "l"(a), "l"(b))

// ---------------- init ----------------
__global__ void init_kernel(const int* __restrict__ z, const float* __restrict__ emb) {
    int idx = blockIdx.x * blockDim.x + threadIdx.x;
    if (idx < N_ATOMS) g_deg[idx] = 0;
    if (idx < 3 * NA64) g_vh2[idx] = __half2half2(__float2half(0.f));
    if (idx >= NV) return;
    int n = idx >> 7;
    int j = idx & 127;
    float s = emb[z[n] * HID + j];
    g_s[idx] = s;
    ((__half*)g_sh2)[n * 128 + ((j & 63) << 1) + (j >> 6)] = __float2half(s);
    g_v[idx] = 0.0f; g_v[NV + idx] = 0.0f; g_v[2 * NV + idx] = 0.0f;
}

// ---------------- CSR build ----------------
__global__ void hist_kernel(const int* __restrict__ ei) {
    int e = blockIdx.x * blockDim.x + threadIdx.x;
    if (e >= N_EDGES) return;
    atomicAdd(&g_deg[ei[e]], 1);
}

#define SCAN_B 512
__global__ void scan1_kernel() {
    __shared__ int s[SCAN_B];
    int t = threadIdx.x;
    int i = blockIdx.x * SCAN_B + t;
    int v = (i < N_ATOMS) ? g_deg[i] : 0;
    s[t] = v;
    __syncthreads();
    for (int off = 1; off < SCAN_B; off <<= 1) {
        int add = (t >= off) ? s[t - off] : 0;
        __syncthreads();
        s[t] += add;
        __syncthreads();
    }
    if (i < N_ATOMS) g_rowptr[i] = s[t] - v;
    if (t == SCAN_B - 1) g_bsum[blockIdx.x] = s[t];
}

__global__ void scan2_kernel(int nblocks) {
    if (threadIdx.x == 0) {
        int run = 0;
        for (int b = 0; b < nblocks; b++) {
            int t = g_bsum[b];
            g_bsum[b] = run;
            run += t;
        }
    }
}

__global__ void scan3_kernel() {
    int i = blockIdx.x * blockDim.x + threadIdx.x;
    if (i < N_ATOMS) {
        int rp = g_rowptr[i] + g_bsum[i >> 9];
        g_rowptr[i] = rp;
        g_cursor[i] = rp;
    }
    if (i == 0) g_rowptr[N_ATOMS] = N_EDGES;
}

__global__ void scatter_kernel(const int* __restrict__ ei, const float* __restrict__ pos) {
    int e = blockIdx.x * blockDim.x + threadIdx.x;
    if (e >= N_EDGES) return;
    int r = ei[e];
    int c = ei[N_EDGES + e];
    float dx = pos[c * 3 + 0] - pos[r * 3 + 0];
    float dy = pos[c * 3 + 1] - pos[r * 3 + 1];
    float dz = pos[c * 3 + 2] - pos[r * 3 + 2];
    float dist = sqrtf(dx * dx + dy * dy + dz * dz);
    float inv = 1.0f / (dist + 1e-8f);
    int p = atomicAdd(&g_cursor[r], 1);
    g_ecol[p] = c;
    g_egeo[p] = make_float4(dx * inv, dy * inv, dz * inv, dist);
}

// ---------------- filter table build (fp32 math, half2 endpoint store) ----------------
#define TAB_SMEM_FLOATS 20736

extern "C" __global__ void __launch_bounds__(512, 1)
table_kernel(const float* __restrict__ fW1, const float* __restrict__ fb1,
             const float* __restrict__ fW2, const float* __restrict__ fb2) {
    extern __shared__ float sm[];
    float* hid = sm;                 // [64][132]
    float* rbf_s = sm + 8448;        // [64][20]
    float* w1_s = sm + 9728;         // [20][128]
    float* w2_s = sm + 8448;         // [32][384] (stage2, overlaps)

    const int tid = threadIdx.x;
    const int layer = blockIdx.y;
    const int g0 = blockIdx.x * 64;
    const float* W1 = fW1 + layer * NRBF * HID;
    const float* b1 = fb1 + layer * HID;
    const float* W2 = fW2 + layer * HID * 3 * HID;
    const float* b2 = fb2 + layer * 3 * HID;
    const float DELTA = TAB_MAX / (float)(TAB_D - 1);

    for (int idx = tid; idx < 64 * NRBF; idx += 512) {
        int e = idx / NRBF, k = idx % NRBF;
        float d = (float)(g0 + e) * DELTA - RBF_STEP * (float)k;
        rbf_s[idx] = expf(-d * d);
    }
    for (int idx = tid; idx < NRBF * HID; idx += 512) w1_s[idx] = W1[idx];
    __syncthreads();

    const int jg = tid & 31;
    const int eg = tid >> 5;
    const int j0 = jg * 4;
    const int el0 = eg * 4;

    float hacc[4][4];
#pragma unroll
    for (int a = 0; a < 4; a++)
#pragma unroll
        for (int b = 0; b < 4; b++) hacc[a][b] = b1[j0 + b];
#pragma unroll
    for (int k = 0; k < NRBF; k++) {
        float r[4];
#pragma unroll
        for (int a = 0; a < 4; a++) r[a] = rbf_s[(el0 + a) * NRBF + k];
        float4 w = *(const float4*)&w1_s[k * HID + j0];
        float wv[4] = {w.x, w.y, w.z, w.w};
#pragma unroll
        for (int a = 0; a < 4; a++)
#pragma unroll
            for (int b = 0; b < 4; b++) hacc[a][b] += r[a] * wv[b];
    }
#pragma unroll
    for (int a = 0; a < 4; a++)
#pragma unroll
        for (int b = 0; b < 4; b++) hid[(el0 + a) * 132 + j0 + b] = silu_f(hacc[a][b]);
    __syncthreads();

    float a_ss[4][4], a_vv[4][4], a_sv[4][4];
#pragma unroll
    for (int a = 0; a < 4; a++)
#pragma unroll
        for (int b = 0; b < 4; b++) { a_ss[a][b] = 0.f; a_vv[a][b] = 0.f; a_sv[a][b] = 0.f; }

    for (int kc = 0; kc < HID; kc += 32) {
        __syncthreads();
        for (int idx = tid; idx < 32 * 384; idx += 512) w2_s[idx] = W2[kc * 384 + idx];
        __syncthreads();
#pragma unroll 8
        for (int kk = 0; kk < 32; kk++) {
            float h[4];
#pragma unroll
            for (int a = 0; a < 4; a++) h[a] = hid[(el0 + a) * 132 + kc + kk];
            float4 wss = *(const float4*)&w2_s[kk * 384 + j0];
            float4 wvv = *(const float4*)&w2_s[kk * 384 + 128 + j0];
            float4 wsv = *(const float4*)&w2_s[kk * 384 + 256 + j0];
            float ss[4] = {wss.x, wss.y, wss.z, wss.w};
            float vv[4] = {wvv.x, wvv.y, wvv.z, wvv.w};
            float sv[4] = {wsv.x, wsv.y, wsv.z, wsv.w};
#pragma unroll
            for (int a = 0; a < 4; a++)
#pragma unroll
                for (int b = 0; b < 4; b++) {
                    a_ss[a][b] += h[a] * ss[b];
                    a_vv[a][b] += h[a] * vv[b];
                    a_sv[a][b] += h[a] * sv[b];
                }
        }
    }

#pragma unroll
    for (int a = 0; a < 4; a++) {
        int gi = g0 + el0 + a;
        __half* Tx = (__half*)(g_htabh + ((size_t)layer * TAB_D + gi) * 384);
        __half* Ty = (__half*)(g_htabh + ((size_t)layer * TAB_D + gi - 1) * 384);
#pragma unroll
        for (int b = 0; b < 4; b++) {
            float hss = a_ss[a][b] + b2[j0 + b];
            float hvv = a_vv[a][b] + b2[128 + j0 + b];
            float hsv = a_sv[a][b] + b2[256 + j0 + b];
            Tx[(j0 + b) * 2]         = __float2half(hss);
            Tx[(128 + j0 + b) * 2]   = __float2half(hvv);
            Tx[(256 + j0 + b) * 2]   = __float2half(hsv);
            if (gi > 0) {
                Ty[(j0 + b) * 2 + 1]       = __float2half(hss);
                Ty[(128 + j0 + b) * 2 + 1] = __float2half(hvv);
                Ty[(256 + j0 + b) * 2 + 1] = __float2half(hsv);
            }
        }
    }
}

// ---------------- edge message kernel: CSR segment-sum, warp per row ----------------
// channels per lane: b0=lane, b1=lane+32, b2=lane+64, b3=lane+96
// sh2[n*64+i] = (s[i], s[i+64]) : i=lane -> (b0,b2), i=lane+32 -> (b1,b3)
extern "C" __global__ void __launch_bounds__(256)
msg_kernel(int layer) {
    int r = (blockIdx.x * 256 + threadIdx.x) >> 5;
    int lane = threadIdx.x & 31;
    if (r >= N_ATOMS) return;

    int beg = g_rowptr[r];
    int end = g_rowptr[r + 1];

    const float INV_DELTA = (float)(TAB_D - 1) / TAB_MAX;
    const __half2* Tl = g_htabh + (size_t)layer * TAB_D * 384;
    const bool hasv = (layer != 0);

    float accS[4] = {0.f, 0.f, 0.f, 0.f};
    float accV[12];
#pragma unroll
    for (int q = 0; q < 12; q++) accV[q] = 0.f;

    for (int p = beg; p < end; p++) {
        int col = g_ecol[p];
        float4 geo = g_egeo[p];
        float u = geo.w * INV_DELTA;
        int i0 = (int)u;
        if (i0 > TAB_D - 2) i0 = TAB_D - 2;
        float f = u - (float)i0;
        const __half2* T = Tl + (size_t)i0 * 384;

        float2 sA = __half22float2(__ldcg(&g_sh2[col * 64 + lane]));
        float2 sB = __half22float2(__ldcg(&g_sh2[col * 64 + 32 + lane]));
        float sc[4] = {sA.x, sB.x, sA.y, sB.y};

        float vc[12];
        if (hasv) {
#pragma unroll
            for (int d = 0; d < 3; d++) {
                float2 vA = __half22float2(__ldcg(&g_vh2[d * NA64 + col * 64 + lane]));
                float2 vB = __half22float2(__ldcg(&g_vh2[d * NA64 + col * 64 + 32 + lane]));
                vc[d * 4 + 0] = vA.x; vc[d * 4 + 1] = vB.x;
                vc[d * 4 + 2] = vA.y; vc[d * 4 + 3] = vB.y;
            }
        }

#pragma unroll
        for (int b = 0; b < 4; b++) {
            int j = lane + 32 * b;
            float2 pss = __half22float2(__ldcg(&T[j]));
            float2 pvv = __half22float2(__ldcg(&T[128 + j]));
            float2 psv = __half22float2(__ldcg(&T[256 + j]));
            float hss = pss.x + f * (pss.y - pss.x);
            float hvv = pvv.x + f * (pvv.y - pvv.x);
            float hsv = psv.x + f * (psv.y - psv.x);
            accS[b] += hss * sc[b];
            float cc = hsv * sc[b];
            if (hasv) {
                accV[b]     += hvv * vc[b]     + cc * geo.x;
                accV[4 + b] += hvv * vc[4 + b] + cc * geo.y;
                accV[8 + b] += hvv * vc[8 + b] + cc * geo.z;
            } else {
                accV[b]     += cc * geo.x;
                accV[4 + b] += cc * geo.y;
                accV[8 + b] += cc * geo.z;
            }
        }
    }

#pragma unroll
    for (int b = 0; b < 4; b++) {
        int j = lane + 32 * b;
        g_ms[r * HID + j] = accS[b];
        float mx = accV[b], my = accV[4 + b], mz = accV[8 + b];
        g_vn[r * HID + j] = sqrtf(mx * mx + my * my + mz * mz);
        g_mv[r * HID + j] = mx;
        g_mv[NV + r * HID + j] = my;
        g_mv[2 * NV + r * HID + j] = mz;
    }
}

// ---------------- node update kernel (f32x2 FMA, half-mirror epilogue) ----------------
#define NT 64
#define XS_STRIDE 76
#define NODE_SMEM_FLOATS 22784

extern "C" __global__ void __launch_bounds__(256, 2)
node_kernel(int layer,
            const float* __restrict__ uW1, const float* __restrict__ ub1,
            const float* __restrict__ uW2, const float* __restrict__ ub2) {
    extern __shared__ float sm[];
    float* xs_t = sm;              // [64 k][76]
    float* wc   = sm + 4864;       // [64 k][128]
    float* ts_t = sm + 13056;      // [128 k][76]

    const int tid = threadIdx.x;
    const int n0 = blockIdx.x * NT;
    const float* W1 = uW1 + layer * 384 * HID;
    const float* b1 = ub1 + layer * HID;
    const float* W2 = uW2 + layer * HID * 384;
    const float* b2 = ub2 + layer * 384;

    const int og = tid & 31;
    const int ng = tid >> 5;
    const int j0 = og * 4;
    const int nl0 = ng * 8;

    float4 wreg[8];
#pragma unroll
    for (int q = 0; q < 8; q++) {
        int idx = q * 256 + tid;
        int k = idx >> 5, c4 = idx & 31;
        wreg[q] = *(const float4*)&W1[k * HID + c4 * 4];
    }

    // ---- stage 1: t = silu(x @ W1 + b1) ----
    float4 b1v = *(const float4*)&b1[j0];
    ull accP[4][4];
    {
        float bb[4] = {b1v.x, b1v.y, b1v.z, b1v.w};
#pragma unroll
        for (int ap = 0; ap < 4; ap++)
#pragma unroll
            for (int b = 0; b < 4; b++) accP[ap][b] = pack2(bb[b], bb[b]);
    }

    for (int kc = 0; kc < 384; kc += 64) {
        __syncthreads();
#pragma unroll
        for (int q = 0; q < 8; q++) {
            int idx = q * 256 + tid;
            int k = idx >> 5, c4 = idx & 31;
            *(float4*)&wc[k * 128 + c4 * 4] = wreg[q];
        }
        for (int idx = tid; idx < 64 * 64; idx += 256) {
            int node = idx >> 6, k = idx & 63;
            int gk = kc + k, gn = n0 + node;
            float val = 0.f;
            if (gn < N_ATOMS) {
                if (gk < 128)      val = g_s[gn * HID + gk];
                else if (gk < 256) val = g_ms[gn * HID + (gk - 128)];
                else               val = g_vn[gn * HID + (gk - 256)];
            }
            xs_t[k * XS_STRIDE + node] = val;
        }
        __syncthreads();
        if (kc + 64 < 384) {
#pragma unroll
            for (int q = 0; q < 8; q++) {
                int idx = q * 256 + tid;
                int k = idx >> 5, c4 = idx & 31;
                wreg[q] = *(const float4*)&W1[(kc + 64 + k) * HID + c4 * 4];
            }
        } else {
#pragma unroll
            for (int q = 0; q < 8; q++) {
                int idx = q * 256 + tid;
                int k = idx >> 5, c4 = idx & 31;
                wreg[q] = *(const float4*)&W2[k * 384 + c4 * 4];
            }
        }
#pragma unroll 4
        for (int kk = 0; kk < 64; kk++) {
            const ull* ax = (const ull*)&xs_t[kk * XS_STRIDE + nl0];
            ull a0 = ax[0], a1 = ax[1], a2 = ax[2], a3 = ax[3];
            float4 w = *(const float4*)&wc[kk * 128 + j0];
            ull w0 = pack2(w.x, w.x), w1 = pack2(w.y, w.y);
            ull w2 = pack2(w.z, w.z), w3 = pack2(w.w, w.w);
            FMA_F32X2(accP[0][0], a0, w0); FMA_F32X2(accP[1][0], a1, w0);
            FMA_F32X2(accP[2][0], a2, w0); FMA_F32X2(accP[3][0], a3, w0);
            FMA_F32X2(accP[0][1], a0, w1); FMA_F32X2(accP[1][1], a1, w1);
            FMA_F32X2(accP[2][1], a2, w1); FMA_F32X2(accP[3][1], a3, w1);
            FMA_F32X2(accP[0][2], a0, w2); FMA_F32X2(accP[1][2], a1, w2);
            FMA_F32X2(accP[2][2], a2, w2); FMA_F32X2(accP[3][2], a3, w2);
            FMA_F32X2(accP[0][3], a0, w3); FMA_F32X2(accP[1][3], a1, w3);
            FMA_F32X2(accP[2][3], a2, w3); FMA_F32X2(accP[3][3], a3, w3);
        }
    }
#pragma unroll
    for (int ap = 0; ap < 4; ap++)
#pragma unroll
        for (int b = 0; b < 4; b++) {
            float lo, hi;
            unpack2(accP[ap][b], lo, hi);
            ts_t[(j0 + b) * XS_STRIDE + nl0 + 2 * ap] = silu_f(lo);
            ts_t[(j0 + b) * XS_STRIDE + nl0 + 2 * ap + 1] = silu_f(hi);
        }

    ull u2P[4][4];
    for (int c = 0; c < 6; c++) {
        int jb = c >> 1;
        int kc2 = (c & 1) * 64;
        if (kc2 == 0) {
#pragma unroll
            for (int ap = 0; ap < 4; ap++)
#pragma unroll
                for (int b = 0; b < 4; b++) u2P[ap][b] = 0ull;
        }
        __syncthreads();
#pragma unroll
        for (int q = 0; q < 8; q++) {
            int idx = q * 256 + tid;
            int k = idx >> 5, c4 = idx & 31;
            *(float4*)&wc[k * 128 + c4 * 4] = wreg[q];
        }
        __syncthreads();
        if (c < 5) {
            int cn = c + 1;
            int jbn = cn >> 1;
            int kc2n = (cn & 1) * 64;
#pragma unroll
            for (int q = 0; q < 8; q++) {
                int idx = q * 256 + tid;
                int k = idx >> 5, c4 = idx & 31;
                wreg[q] = *(const float4*)&W2[(kc2n + k) * 384 + jbn * 128 + c4 * 4];
            }
        }
#pragma unroll 4
        for (int kk = 0; kk < 64; kk++) {
            const ull* ax = (const ull*)&ts_t[(kc2 + kk) * XS_STRIDE + nl0];
            ull a0 = ax[0], a1 = ax[1], a2 = ax[2], a3 = ax[3];
            float4 w = *(const float4*)&wc[kk * 128 + j0];
            ull w0 = pack2(w.x, w.x), w1 = pack2(w.y, w.y);
            ull w2 = pack2(w.z, w.z), w3 = pack2(w.w, w.w);
            FMA_F32X2(u2P[0][0], a0, w0); FMA_F32X2(u2P[1][0], a1, w0);
            FMA_F32X2(u2P[2][0], a2, w0); FMA_F32X2(u2P[3][0], a3, w0);
            FMA_F32X2(u2P[0][1], a0, w1); FMA_F32X2(u2P[1][1], a1, w1);
            FMA_F32X2(u2P[2][1], a2, w1); FMA_F32X2(u2P[3][1], a3, w1);
            FMA_F32X2(u2P[0][2], a0, w2); FMA_F32X2(u2P[1][2], a1, w2);
            FMA_F32X2(u2P[2][2], a2, w2); FMA_F32X2(u2P[3][2], a3, w2);
            FMA_F32X2(u2P[0][3], a0, w3); FMA_F32X2(u2P[1][3], a1, w3);
            FMA_F32X2(u2P[2][3], a2, w3); FMA_F32X2(u2P[3][3], a3, w3);
        }

        if (kc2 == 64) {
            float u2[8][4];
#pragma unroll
            for (int ap = 0; ap < 4; ap++)
#pragma unroll
                for (int b = 0; b < 4; b++)
                    unpack2(u2P[ap][b], u2[2 * ap][b], u2[2 * ap + 1][b]);

            float4 b2v = *(const float4*)&b2[jb * 128 + j0];
            float bb[4] = {b2v.x, b2v.y, b2v.z, b2v.w};
#pragma unroll
            for (int a = 0; a < 8; a++) {
                int gn = n0 + nl0 + a;
                bool valid = (gn < N_ATOMS);
                if (jb == 0) {
                    float sn[4] = {0.f, 0.f, 0.f, 0.f};
                    if (valid) {
#pragma unroll
                        for (int b = 0; b < 4; b++) {
                            sn[b] = g_s[gn * HID + j0 + b] + u2[a][b] + bb[b];
                            g_s[gn * HID + j0 + b] = sn[b];
                        }
                    }
                    // half mirror: pair (j, j+64) via lane og <-> og+16
                    __half2 hp[4];
#pragma unroll
                    for (int b = 0; b < 4; b++) {
                        float other = __shfl_xor_sync(0xffffffffu, sn[b], 16);
                        hp[b] = __floats2half2_rn(sn[b], other);
                    }
                    if (valid && og < 16)
                        *(uint4*)&g_sh2[gn * 64 + j0] = *(uint4*)hp;
                } else if (jb == 1) {
                    if (valid) {
#pragma unroll
                        for (int d = 0; d < 3; d++) {
                            const float4 vi = *(const float4*)&g_v[d * NV + gn * HID + j0];
                            float4 vv;
                            vv.x = vi.x * (u2[a][0] + bb[0]);
                            vv.y = vi.y * (u2[a][1] + bb[1]);
                            vv.z = vi.z * (u2[a][2] + bb[2]);
                            vv.w = vi.w * (u2[a][3] + bb[3]);
                            *(float4*)&g_v[d * NV + gn * HID + j0] = vv;
                        }
                    }
                } else {
#pragma unroll
                    for (int d = 0; d < 3; d++) {
                        float4 vv = make_float4(0.f, 0.f, 0.f, 0.f);
                        if (valid) {
                            float4 vp = *(const float4*)&g_v[d * NV + gn * HID + j0];
                            const float4 mv = *(const float4*)&g_mv[d * NV + gn * HID + j0];
                            vv.x = vp.x + (u2[a][0] + bb[0]) * mv.x;
                            vv.y = vp.y + (u2[a][1] + bb[1]) * mv.y;
                            vv.z = vp.z + (u2[a][2] + bb[2]) * mv.z;
                            vv.w = vp.w + (u2[a][3] + bb[3]) * mv.w;
                            *(float4*)&g_v[d * NV + gn * HID + j0] = vv;
                        }
                        __half2 hp[4];
                        float o0 = __shfl_xor_sync(0xffffffffu, vv.x, 16);
                        float o1 = __shfl_xor_sync(0xffffffffu, vv.y, 16);
                        float o2 = __shfl_xor_sync(0xffffffffu, vv.z, 16);
                        float o3 = __shfl_xor_sync(0xffffffffu, vv.w, 16);
                        hp[0] = __floats2half2_rn(vv.x, o0);
                        hp[1] = __floats2half2_rn(vv.y, o1);
                        hp[2] = __floats2half2_rn(vv.z, o2);
                        hp[3] = __floats2half2_rn(vv.w, o3);
                        if (valid && og < 16)
                            *(uint4*)&g_vh2[d * NA64 + gn * 64 + j0] = *(uint4*)hp;
                    }
                }
            }
        }
    }
}

// ---------------- molecule pooling + heads ----------------
__global__ void pool_zero_kernel() {
    int idx = blockIdx.x * blockDim.x + threadIdx.x;
    if (idx < N_MOLS * HID) g_hmol[idx] = 0.f;
    if (idx < N_MOLS) g_cnt[idx] = 0.f;
}

__global__ void pool_acc_kernel(const int* __restrict__ batch) {
    int idx = blockIdx.x * blockDim.x + threadIdx.x;
    if (idx >= NV) return;
    int n = idx >> 7;
    int j = idx & 127;
    int m = batch[n];
    atomicAdd(&g_hmol[m * HID + j], g_s[idx]);
    if (j == 0) atomicAdd(&g_cnt[m], 1.0f);
}

__global__ void head_kernel(const float* __restrict__ lW1, const float* __restrict__ lb1,
                            const float* __restrict__ lW2, const float* __restrict__ lb2,
                            const float* __restrict__ pW1, const float* __restrict__ pb1,
                            const float* __restrict__ pW2, const float* __restrict__ pb2,
                            float* __restrict__ out) {
    __shared__ float hm[HID];
    __shared__ float tt[HID];
    __shared__ float red[HID];
    int m = blockIdx.x;
    int j = threadIdx.x;
    float cnt = g_cnt[m];
    hm[j] = g_hmol[m * HID + j] / cnt;
    __syncthreads();

    float acc = lb1[j];
    for (int k = 0; k < HID; k++) acc += hm[k] * lW1[k * HID + j];
    tt[j] = silu_f(acc);
    __syncthreads();
    red[j] = tt[j] * lW2[j];
    __syncthreads();
    for (int s = 64; s > 0; s >>= 1) {
        if (j < s) red[j] += red[j + s];
        __syncthreads();
    }
    if (j == 0) out[m] = red[0] + lb2[0];
    __syncthreads();

    acc = pb1[j];
    for (int k = 0; k < HID; k++) acc += hm[k] * pW1[k * HID + j];
    tt[j] = silu_f(acc);
    __syncthreads();
    red[j] = tt[j] * pW2[j];
    __syncthreads();
    for (int s = 64; s > 0; s >>= 1) {
        if (j < s) red[j] += red[j + s];
        __syncthreads();
    }
    if (j == 0) {
        float x = red[0] + pb2[0];
        out[N_MOLS + m] = 1.0f / (1.0f + expf(-x));
    }
}

// ---------------- launch ----------------
extern "C" void kernel_launch(void* const* d_in, const int* in_sizes, int n_in,
                              void* d_out, int out_size) {
    const int* z = (const int*)d_in[0];
    const float* pos = (const float*)d_in[1];
    const int* ei = (const int*)d_in[2];
    const int* batch = (const int*)d_in[3];
    const float* emb = (const float*)d_in[4];
    const float* fW1 = (const float*)d_in[5];
    const float* fb1 = (const float*)d_in[6];
    const float* fW2 = (const float*)d_in[7];
    const float* fb2 = (const float*)d_in[8];
    const float* uW1 = (const float*)d_in[9];
    const float* ub1 = (const float*)d_in[10];
    const float* uW2 = (const float*)d_in[11];
    const float* ub2 = (const float*)d_in[12];
    const float* lW1 = (const float*)d_in[13];
    const float* lb1 = (const float*)d_in[14];
    const float* lW2 = (const float*)d_in[15];
    const float* lb2 = (const float*)d_in[16];
    const float* pW1 = (const float*)d_in[17];
    const float* pb1 = (const float*)d_in[18];
    const float* pW2 = (const float*)d_in[19];
    const float* pb2 = (const float*)d_in[20];
    float* out = (float*)d_out;

    cudaFuncSetAttribute(table_kernel, cudaFuncAttributeMaxDynamicSharedMemorySize,
                         TAB_SMEM_FLOATS * 4);
    cudaFuncSetAttribute(node_kernel, cudaFuncAttributeMaxDynamicSharedMemorySize,
                         NODE_SMEM_FLOATS * 4);

    init_kernel<<<(3 * NA64 + 255) / 256, 256>>>(z, emb);

    const int scan_blocks = (N_ATOMS + SCAN_B - 1) / SCAN_B;
    hist_kernel<<<(N_EDGES + 255) / 256, 256>>>(ei);
    scan1_kernel<<<scan_blocks, SCAN_B>>>();
    scan2_kernel<<<1, 32>>>(scan_blocks);
    scan3_kernel<<<(N_ATOMS + 255) / 256, 256>>>();
    scatter_kernel<<<(N_EDGES + 255) / 256, 256>>>(ei, pos);

    table_kernel<<<dim3(TAB_D / 64, NLAYERS), 512, TAB_SMEM_FLOATS * 4>>>(fW1, fb1, fW2, fb2);

    const int msg_blocks = (N_ATOMS * 32 + 255) / 256;
    const int node_blocks = (N_ATOMS + NT - 1) / NT;
    for (int layer = 0; layer < NLAYERS; layer++) {
        msg_kernel<<<msg_blocks, 256>>>(layer);
        node_kernel<<<node_blocks, 256, NODE_SMEM_FLOATS * 4>>>(layer, uW1, ub1, uW2, ub2);
    }

    pool_zero_kernel<<<(N_MOLS * HID + 255) / 256, 256>>>();
    pool_acc_kernel<<<(NV + 255) / 256, 256>>>(batch);
    head_kernel<<<N_MOLS, HID>>>(lW1, lb1, lW2, lb2, pW1, pb1, pW2, pb2, out);
}

// round 8
// speedup vs baseline: 1.7504x; 1.3557x over previous
#include <cuda_runtime.h>
#include <cuda_fp16.h>
#include <math.h>

#define N_ATOMS 50000
#define N_EDGES 400000
#define N_MOLS  500
#define HID     128
#define NRBF    20
#define NLAYERS 4
#define NV      (N_ATOMS * HID)
#define NA64    (N_ATOMS * 64)

#define TAB_D   2048
#define TAB_MAX 12.0f
#define RBF_STEP (5.0f / (float)(NRBF - 1))

typedef unsigned long long ull;

// ---------------- device scratch ----------------
__device__ float g_s[NV];
__device__ float g_v[3 * NV];          // planar [3][N][HID] fp32 masters
__device__ __half2 g_sh2[NA64];        // packed (s[j], s[j+64]) at [n*64 + j], j<64
__device__ __half2 g_vh2[3 * NA64];    // same packing per plane
__device__ float g_ms[NV];
__device__ float g_vn[NV];             // ||m_v||
__device__ float g_mv[3 * NV];
__device__ __half2 g_htabh[NLAYERS * TAB_D * 3 * HID];  // (.x=h(i), .y=h(i+1))
__device__ float g_hmol[N_MOLS * HID];
__device__ float g_cnt[N_MOLS];

// CSR scratch
__device__ int   g_deg[N_ATOMS];
__device__ int   g_rowptr[N_ATOMS + 1];
__device__ int   g_cursor[N_ATOMS];
__device__ int   g_bsum[128];
__device__ int   g_ecol[N_EDGES];
__device__ float4 g_egeo[N_EDGES];     // (dirx, diry, dirz, dist*INV_DELTA)

__device__ __forceinline__ float silu_f(float x) { return x / (1.0f + expf(-x)); }

__device__ __forceinline__ ull pack2(float lo, float hi) {
    ull r;
    asm("mov.b64 %0, {%1, %2};" : "=l"(r) : "f"(lo), "f"(hi));
    return r;
}
__device__ __forceinline__ void unpack2(ull v, float& lo, float& hi) {
    asm("mov.b64 {%0, %1}, %2;" : "=f"(lo), "=f"(hi) : "l"(v));
}
#define FMA_F32X2(acc, a, b) \
    asm("fma.rn.f32x2 %0, %1, %2, %0;" : "+l"(acc) : "l"(a), "l"(b))

// ---------------- init ----------------
__global__ void init_kernel(const int* __restrict__ z, const float* __restrict__ emb) {
    int idx = blockIdx.x * blockDim.x + threadIdx.x;
    if (idx < N_ATOMS) g_deg[idx] = 0;
    if (idx < 3 * NA64) g_vh2[idx] = __half2half2(__float2half(0.f));
    if (idx >= NV) return;
    int n = idx >> 7;
    int j = idx & 127;
    float s = emb[z[n] * HID + j];
    g_s[idx] = s;
    ((__half*)g_sh2)[n * 128 + ((j & 63) << 1) + (j >> 6)] = __float2half(s);
    g_v[idx] = 0.0f; g_v[NV + idx] = 0.0f; g_v[2 * NV + idx] = 0.0f;
}

// ---------------- CSR build ----------------
__global__ void hist_kernel(const int* __restrict__ ei) {
    int e = blockIdx.x * blockDim.x + threadIdx.x;
    if (e >= N_EDGES) return;
    atomicAdd(&g_deg[ei[e]], 1);
}

#define SCAN_B 512
__global__ void scan1_kernel() {
    __shared__ int s[SCAN_B];
    int t = threadIdx.x;
    int i = blockIdx.x * SCAN_B + t;
    int v = (i < N_ATOMS) ? g_deg[i] : 0;
    s[t] = v;
    __syncthreads();
    for (int off = 1; off < SCAN_B; off <<= 1) {
        int add = (t >= off) ? s[t - off] : 0;
        __syncthreads();
        s[t] += add;
        __syncthreads();
    }
    if (i < N_ATOMS) g_rowptr[i] = s[t] - v;
    if (t == SCAN_B - 1) g_bsum[blockIdx.x] = s[t];
}

__global__ void scan2_kernel(int nblocks) {
    if (threadIdx.x == 0) {
        int run = 0;
        for (int b = 0; b < nblocks; b++) {
            int t = g_bsum[b];
            g_bsum[b] = run;
            run += t;
        }
    }
}

__global__ void scan3_kernel() {
    int i = blockIdx.x * blockDim.x + threadIdx.x;
    if (i < N_ATOMS) {
        int rp = g_rowptr[i] + g_bsum[i >> 9];
        g_rowptr[i] = rp;
        g_cursor[i] = rp;
    }
    if (i == 0) g_rowptr[N_ATOMS] = N_EDGES;
}

__global__ void scatter_kernel(const int* __restrict__ ei, const float* __restrict__ pos) {
    int e = blockIdx.x * blockDim.x + threadIdx.x;
    if (e >= N_EDGES) return;
    int r = ei[e];
    int c = ei[N_EDGES + e];
    float dx = pos[c * 3 + 0] - pos[r * 3 + 0];
    float dy = pos[c * 3 + 1] - pos[r * 3 + 1];
    float dz = pos[c * 3 + 2] - pos[r * 3 + 2];
    float dist = sqrtf(dx * dx + dy * dy + dz * dz);
    float inv = 1.0f / (dist + 1e-8f);
    const float INV_DELTA = (float)(TAB_D - 1) / TAB_MAX;
    int p = atomicAdd(&g_cursor[r], 1);
    g_ecol[p] = c;
    g_egeo[p] = make_float4(dx * inv, dy * inv, dz * inv, dist * INV_DELTA);
}

// ---------------- filter table build (fp32 math, half2 endpoint store) ----------------
#define TAB_SMEM_FLOATS 20736

extern "C" __global__ void __launch_bounds__(512, 1)
table_kernel(const float* __restrict__ fW1, const float* __restrict__ fb1,
             const float* __restrict__ fW2, const float* __restrict__ fb2) {
    extern __shared__ float sm[];
    float* hid = sm;                 // [64][132]
    float* rbf_s = sm + 8448;        // [64][20]
    float* w1_s = sm + 9728;         // [20][128]
    float* w2_s = sm + 8448;         // [32][384] (stage2, overlaps)

    const int tid = threadIdx.x;
    const int layer = blockIdx.y;
    const int g0 = blockIdx.x * 64;
    const float* W1 = fW1 + layer * NRBF * HID;
    const float* b1 = fb1 + layer * HID;
    const float* W2 = fW2 + layer * HID * 3 * HID;
    const float* b2 = fb2 + layer * 3 * HID;
    const float DELTA = TAB_MAX / (float)(TAB_D - 1);

    for (int idx = tid; idx < 64 * NRBF; idx += 512) {
        int e = idx / NRBF, k = idx % NRBF;
        float d = (float)(g0 + e) * DELTA - RBF_STEP * (float)k;
        rbf_s[idx] = expf(-d * d);
    }
    for (int idx = tid; idx < NRBF * HID; idx += 512) w1_s[idx] = W1[idx];
    __syncthreads();

    const int jg = tid & 31;
    const int eg = tid >> 5;
    const int j0 = jg * 4;
    const int el0 = eg * 4;

    float hacc[4][4];
#pragma unroll
    for (int a = 0; a < 4; a++)
#pragma unroll
        for (int b = 0; b < 4; b++) hacc[a][b] = b1[j0 + b];
#pragma unroll
    for (int k = 0; k < NRBF; k++) {
        float r[4];
#pragma unroll
        for (int a = 0; a < 4; a++) r[a] = rbf_s[(el0 + a) * NRBF + k];
        float4 w = *(const float4*)&w1_s[k * HID + j0];
        float wv[4] = {w.x, w.y, w.z, w.w};
#pragma unroll
        for (int a = 0; a < 4; a++)
#pragma unroll
            for (int b = 0; b < 4; b++) hacc[a][b] += r[a] * wv[b];
    }
#pragma unroll
    for (int a = 0; a < 4; a++)
#pragma unroll
        for (int b = 0; b < 4; b++) hid[(el0 + a) * 132 + j0 + b] = silu_f(hacc[a][b]);
    __syncthreads();

    float a_ss[4][4], a_vv[4][4], a_sv[4][4];
#pragma unroll
    for (int a = 0; a < 4; a++)
#pragma unroll
        for (int b = 0; b < 4; b++) { a_ss[a][b] = 0.f; a_vv[a][b] = 0.f; a_sv[a][b] = 0.f; }

    for (int kc = 0; kc < HID; kc += 32) {
        __syncthreads();
        for (int idx = tid; idx < 32 * 384; idx += 512) w2_s[idx] = W2[kc * 384 + idx];
        __syncthreads();
#pragma unroll 8
        for (int kk = 0; kk < 32; kk++) {
            float h[4];
#pragma unroll
            for (int a = 0; a < 4; a++) h[a] = hid[(el0 + a) * 132 + kc + kk];
            float4 wss = *(const float4*)&w2_s[kk * 384 + j0];
            float4 wvv = *(const float4*)&w2_s[kk * 384 + 128 + j0];
            float4 wsv = *(const float4*)&w2_s[kk * 384 + 256 + j0];
            float ss[4] = {wss.x, wss.y, wss.z, wss.w};
            float vv[4] = {wvv.x, wvv.y, wvv.z, wvv.w};
            float sv[4] = {wsv.x, wsv.y, wsv.z, wsv.w};
#pragma unroll
            for (int a = 0; a < 4; a++)
#pragma unroll
                for (int b = 0; b < 4; b++) {
                    a_ss[a][b] += h[a] * ss[b];
                    a_vv[a][b] += h[a] * vv[b];
                    a_sv[a][b] += h[a] * sv[b];
                }
        }
    }

#pragma unroll
    for (int a = 0; a < 4; a++) {
        int gi = g0 + el0 + a;
        __half* Tx = (__half*)(g_htabh + ((size_t)layer * TAB_D + gi) * 384);
        __half* Ty = (__half*)(g_htabh + ((size_t)layer * TAB_D + gi - 1) * 384);
#pragma unroll
        for (int b = 0; b < 4; b++) {
            float hss = a_ss[a][b] + b2[j0 + b];
            float hvv = a_vv[a][b] + b2[128 + j0 + b];
            float hsv = a_sv[a][b] + b2[256 + j0 + b];
            Tx[(j0 + b) * 2]         = __float2half(hss);
            Tx[(128 + j0 + b) * 2]   = __float2half(hvv);
            Tx[(256 + j0 + b) * 2]   = __float2half(hsv);
            if (gi > 0) {
                Ty[(j0 + b) * 2 + 1]       = __float2half(hss);
                Ty[(128 + j0 + b) * 2 + 1] = __float2half(hvv);
                Ty[(256 + j0 + b) * 2 + 1] = __float2half(hsv);
            }
        }
    }
}

// ---------------- edge message kernel: CSR segment-sum, warp per row ----------------
extern "C" __global__ void __launch_bounds__(256)
msg_kernel(int layer) {
    int r = (blockIdx.x * 256 + threadIdx.x) >> 5;
    int lane = threadIdx.x & 31;
    if (r >= N_ATOMS) return;

    int beg = g_rowptr[r];
    int end = g_rowptr[r + 1];
    if (beg >= end) {
#pragma unroll
        for (int b = 0; b < 4; b++) {
            int j = lane + 32 * b;
            g_ms[r * HID + j] = 0.f;
            g_vn[r * HID + j] = 0.f;
            g_mv[r * HID + j] = 0.f;
            g_mv[NV + r * HID + j] = 0.f;
            g_mv[2 * NV + r * HID + j] = 0.f;
        }
        return;
    }

    const __half2* Tl = g_htabh + (size_t)layer * TAB_D * 384;
    const bool hasv = (layer != 0);

    float accS[4] = {0.f, 0.f, 0.f, 0.f};
    float accV[12];
#pragma unroll
    for (int q = 0; q < 12; q++) accV[q] = 0.f;

    int col = g_ecol[beg];
    float4 geo = g_egeo[beg];

    for (int p = beg; p < end; p++) {
        int ncol = 0;
        float4 ngeo = geo;
        if (p + 1 < end) {
            ncol = g_ecol[p + 1];
            ngeo = g_egeo[p + 1];
        }
        float u = geo.w;
        int i0 = (int)u;
        if (i0 > TAB_D - 2) i0 = TAB_D - 2;
        float f = u - (float)i0;
        const __half2* T = Tl + (size_t)i0 * 384;

        float2 sA = __half22float2(__ldcg(&g_sh2[col * 64 + lane]));
        float2 sB = __half22float2(__ldcg(&g_sh2[col * 64 + 32 + lane]));
        float sc[4] = {sA.x, sB.x, sA.y, sB.y};

        float vc[12];
        if (hasv) {
#pragma unroll
            for (int d = 0; d < 3; d++) {
                float2 vA = __half22float2(__ldcg(&g_vh2[d * NA64 + col * 64 + lane]));
                float2 vB = __half22float2(__ldcg(&g_vh2[d * NA64 + col * 64 + 32 + lane]));
                vc[d * 4 + 0] = vA.x; vc[d * 4 + 1] = vB.x;
                vc[d * 4 + 2] = vA.y; vc[d * 4 + 3] = vB.y;
            }
        }

#pragma unroll
        for (int b = 0; b < 4; b++) {
            int j = lane + 32 * b;
            float2 pss = __half22float2(__ldcg(&T[j]));
            float2 pvv = __half22float2(__ldcg(&T[128 + j]));
            float2 psv = __half22float2(__ldcg(&T[256 + j]));
            float hss = pss.x + f * (pss.y - pss.x);
            float hvv = pvv.x + f * (pvv.y - pvv.x);
            float hsv = psv.x + f * (psv.y - psv.x);
            accS[b] += hss * sc[b];
            float cc = hsv * sc[b];
            if (hasv) {
                accV[b]     += hvv * vc[b]     + cc * geo.x;
                accV[4 + b] += hvv * vc[4 + b] + cc * geo.y;
                accV[8 + b] += hvv * vc[8 + b] + cc * geo.z;
            } else {
                accV[b]     += cc * geo.x;
                accV[4 + b] += cc * geo.y;
                accV[8 + b] += cc * geo.z;
            }
        }
        col = ncol;
        geo = ngeo;
    }

#pragma unroll
    for (int b = 0; b < 4; b++) {
        int j = lane + 32 * b;
        g_ms[r * HID + j] = accS[b];
        float mx = accV[b], my = accV[4 + b], mz = accV[8 + b];
        g_vn[r * HID + j] = sqrtf(mx * mx + my * my + mz * mz);
        g_mv[r * HID + j] = mx;
        g_mv[NV + r * HID + j] = my;
        g_mv[2 * NV + r * HID + j] = mz;
    }
}

// ---------------- node update kernel (f32x2 FMA, reg-prefetched x and W) ----------------
#define NT 64
#define XS_STRIDE 76
#define NODE_SMEM_FLOATS 22784

extern "C" __global__ void __launch_bounds__(256, 2)
node_kernel(int layer,
            const float* __restrict__ uW1, const float* __restrict__ ub1,
            const float* __restrict__ uW2, const float* __restrict__ ub2) {
    extern __shared__ float sm[];
    float* xs_t = sm;              // [64 k][76]
    float* wc   = sm + 4864;       // [64 k][128]
    float* ts_t = sm + 13056;      // [128 k][76]

    const int tid = threadIdx.x;
    const int n0 = blockIdx.x * NT;
    const float* W1 = uW1 + layer * 384 * HID;
    const float* b1 = ub1 + layer * HID;
    const float* W2 = uW2 + layer * HID * 384;
    const float* b2 = ub2 + layer * 384;

    const int og = tid & 31;
    const int ng = tid >> 5;
    const int j0 = og * 4;
    const int nl0 = ng * 8;

    // xs staging mapping: thread -> (node, 4 k-quads)
    const int snode = tid & 63;
    const int sq = (tid >> 6) << 2;          // 0,4,8,12
    const int sgn = n0 + snode;
    const bool svalid = (sgn < N_ATOMS);

    float4 wreg[8];
#pragma unroll
    for (int q = 0; q < 8; q++) {
        int idx = q * 256 + tid;
        int k = idx >> 5, c4 = idx & 31;
        wreg[q] = *(const float4*)&W1[k * HID + c4 * 4];
    }

    float4 xpre[4];
    {
        const float* sp = g_s + (size_t)sgn * HID;   // chunk 0: g_s, coloff 0
#pragma unroll
        for (int q = 0; q < 4; q++)
            xpre[q] = svalid ? *(const float4*)&sp[sq + 16 * q]
                             : make_float4(0.f, 0.f, 0.f, 0.f);
    }

    // ---- stage 1: t = silu(x @ W1 + b1) ----
    float4 b1v = *(const float4*)&b1[j0];
    ull accP[4][4];
    {
        float bb[4] = {b1v.x, b1v.y, b1v.z, b1v.w};
#pragma unroll
        for (int ap = 0; ap < 4; ap++)
#pragma unroll
            for (int b = 0; b < 4; b++) accP[ap][b] = pack2(bb[b], bb[b]);
    }

    for (int kc = 0; kc < 384; kc += 64) {
        __syncthreads();
#pragma unroll
        for (int q = 0; q < 8; q++) {
            int idx = q * 256 + tid;
            int k = idx >> 5, c4 = idx & 31;
            *(float4*)&wc[k * 128 + c4 * 4] = wreg[q];
        }
#pragma unroll
        for (int q = 0; q < 4; q++) {
            int kl = sq + 16 * q;
            xs_t[(kl + 0) * XS_STRIDE + snode] = xpre[q].x;
            xs_t[(kl + 1) * XS_STRIDE + snode] = xpre[q].y;
            xs_t[(kl + 2) * XS_STRIDE + snode] = xpre[q].z;
            xs_t[(kl + 3) * XS_STRIDE + snode] = xpre[q].w;
        }
        __syncthreads();
        if (kc + 64 < 384) {
            int nkc = kc + 64;
            const float* src = (nkc < 128) ? g_s : ((nkc < 256) ? g_ms : g_vn);
            const float* sp = src + (size_t)sgn * HID + (nkc & 127);
#pragma unroll
            for (int q = 0; q < 8; q++) {
                int idx = q * 256 + tid;
                int k = idx >> 5, c4 = idx & 31;
                wreg[q] = *(const float4*)&W1[(nkc + k) * HID + c4 * 4];
            }
#pragma unroll
            for (int q = 0; q < 4; q++)
                xpre[q] = svalid ? *(const float4*)&sp[sq + 16 * q]
                                 : make_float4(0.f, 0.f, 0.f, 0.f);
        } else {
#pragma unroll
            for (int q = 0; q < 8; q++) {
                int idx = q * 256 + tid;
                int k = idx >> 5, c4 = idx & 31;
                wreg[q] = *(const float4*)&W2[k * 384 + c4 * 4];
            }
        }
#pragma unroll 4
        for (int kk = 0; kk < 64; kk++) {
            const ull* ax = (const ull*)&xs_t[kk * XS_STRIDE + nl0];
            ull a0 = ax[0], a1 = ax[1], a2 = ax[2], a3 = ax[3];
            float4 w = *(const float4*)&wc[kk * 128 + j0];
            ull w0 = pack2(w.x, w.x), w1 = pack2(w.y, w.y);
            ull w2 = pack2(w.z, w.z), w3 = pack2(w.w, w.w);
            FMA_F32X2(accP[0][0], a0, w0); FMA_F32X2(accP[1][0], a1, w0);
            FMA_F32X2(accP[2][0], a2, w0); FMA_F32X2(accP[3][0], a3, w0);
            FMA_F32X2(accP[0][1], a0, w1); FMA_F32X2(accP[1][1], a1, w1);
            FMA_F32X2(accP[2][1], a2, w1); FMA_F32X2(accP[3][1], a3, w1);
            FMA_F32X2(accP[0][2], a0, w2); FMA_F32X2(accP[1][2], a1, w2);
            FMA_F32X2(accP[2][2], a2, w2); FMA_F32X2(accP[3][2], a3, w2);
            FMA_F32X2(accP[0][3], a0, w3); FMA_F32X2(accP[1][3], a1, w3);
            FMA_F32X2(accP[2][3], a2, w3); FMA_F32X2(accP[3][3], a3, w3);
        }
    }
#pragma unroll
    for (int ap = 0; ap < 4; ap++)
#pragma unroll
        for (int b = 0; b < 4; b++) {
            float lo, hi;
            unpack2(accP[ap][b], lo, hi);
            ts_t[(j0 + b) * XS_STRIDE + nl0 + 2 * ap] = silu_f(lo);
            ts_t[(j0 + b) * XS_STRIDE + nl0 + 2 * ap + 1] = silu_f(hi);
        }

    ull u2P[4][4];
    for (int c = 0; c < 6; c++) {
        int jb = c >> 1;
        int kc2 = (c & 1) * 64;
        if (kc2 == 0) {
#pragma unroll
            for (int ap = 0; ap < 4; ap++)
#pragma unroll
                for (int b = 0; b < 4; b++) u2P[ap][b] = 0ull;
        }
        __syncthreads();
#pragma unroll
        for (int q = 0; q < 8; q++) {
            int idx = q * 256 + tid;
            int k = idx >> 5, c4 = idx & 31;
            *(float4*)&wc[k * 128 + c4 * 4] = wreg[q];
        }
        __syncthreads();
        if (c < 5) {
            int cn = c + 1;
            int jbn = cn >> 1;
            int kc2n = (cn & 1) * 64;
#pragma unroll
            for (int q = 0; q < 8; q++) {
                int idx = q * 256 + tid;
                int k = idx >> 5, c4 = idx & 31;
                wreg[q] = *(const float4*)&W2[(kc2n + k) * 384 + jbn * 128 + c4 * 4];
            }
        }
#pragma unroll 4
        for (int kk = 0; kk < 64; kk++) {
            const ull* ax = (const ull*)&ts_t[(kc2 + kk) * XS_STRIDE + nl0];
            ull a0 = ax[0], a1 = ax[1], a2 = ax[2], a3 = ax[3];
            float4 w = *(const float4*)&wc[kk * 128 + j0];
            ull w0 = pack2(w.x, w.x), w1 = pack2(w.y, w.y);
            ull w2 = pack2(w.z, w.z), w3 = pack2(w.w, w.w);
            FMA_F32X2(u2P[0][0], a0, w0); FMA_F32X2(u2P[1][0], a1, w0);
            FMA_F32X2(u2P[2][0], a2, w0); FMA_F32X2(u2P[3][0], a3, w0);
            FMA_F32X2(u2P[0][1], a0, w1); FMA_F32X2(u2P[1][1], a1, w1);
            FMA_F32X2(u2P[2][1], a2, w1); FMA_F32X2(u2P[3][1], a3, w1);
            FMA_F32X2(u2P[0][2], a0, w2); FMA_F32X2(u2P[1][2], a1, w2);
            FMA_F32X2(u2P[2][2], a2, w2); FMA_F32X2(u2P[3][2], a3, w2);
            FMA_F32X2(u2P[0][3], a0, w3); FMA_F32X2(u2P[1][3], a1, w3);
            FMA_F32X2(u2P[2][3], a2, w3); FMA_F32X2(u2P[3][3], a3, w3);
        }

        if (kc2 == 64) {
            float u2[8][4];
#pragma unroll
            for (int ap = 0; ap < 4; ap++)
#pragma unroll
                for (int b = 0; b < 4; b++)
                    unpack2(u2P[ap][b], u2[2 * ap][b], u2[2 * ap + 1][b]);

            float4 b2v = *(const float4*)&b2[jb * 128 + j0];
            float bb[4] = {b2v.x, b2v.y, b2v.z, b2v.w};
#pragma unroll
            for (int a = 0; a < 8; a++) {
                int gn = n0 + nl0 + a;
                bool valid = (gn < N_ATOMS);
                if (jb == 0) {
                    float sn[4] = {0.f, 0.f, 0.f, 0.f};
                    if (valid) {
#pragma unroll
                        for (int b = 0; b < 4; b++) {
                            sn[b] = g_s[gn * HID + j0 + b] + u2[a][b] + bb[b];
                            g_s[gn * HID + j0 + b] = sn[b];
                        }
                    }
                    __half2 hp[4];
#pragma unroll
                    for (int b = 0; b < 4; b++) {
                        float other = __shfl_xor_sync(0xffffffffu, sn[b], 16);
                        hp[b] = __floats2half2_rn(sn[b], other);
                    }
                    if (valid && og < 16)
                        *(uint4*)&g_sh2[gn * 64 + j0] = *(uint4*)hp;
                } else if (jb == 1) {
                    if (valid) {
#pragma unroll
                        for (int d = 0; d < 3; d++) {
                            const float4 vi = *(const float4*)&g_v[d * NV + gn * HID + j0];
                            float4 vv;
                            vv.x = vi.x * (u2[a][0] + bb[0]);
                            vv.y = vi.y * (u2[a][1] + bb[1]);
                            vv.z = vi.z * (u2[a][2] + bb[2]);
                            vv.w = vi.w * (u2[a][3] + bb[3]);
                            *(float4*)&g_v[d * NV + gn * HID + j0] = vv;
                        }
                    }
                } else {
#pragma unroll
                    for (int d = 0; d < 3; d++) {
                        float4 vv = make_float4(0.f, 0.f, 0.f, 0.f);
                        if (valid) {
                            float4 vp = *(const float4*)&g_v[d * NV + gn * HID + j0];
                            const float4 mv = *(const float4*)&g_mv[d * NV + gn * HID + j0];
                            vv.x = vp.x + (u2[a][0] + bb[0]) * mv.x;
                            vv.y = vp.y + (u2[a][1] + bb[1]) * mv.y;
                            vv.z = vp.z + (u2[a][2] + bb[2]) * mv.z;
                            vv.w = vp.w + (u2[a][3] + bb[3]) * mv.w;
                            *(float4*)&g_v[d * NV + gn * HID + j0] = vv;
                        }
                        __half2 hp[4];
                        float o0 = __shfl_xor_sync(0xffffffffu, vv.x, 16);
                        float o1 = __shfl_xor_sync(0xffffffffu, vv.y, 16);
                        float o2 = __shfl_xor_sync(0xffffffffu, vv.z, 16);
                        float o3 = __shfl_xor_sync(0xffffffffu, vv.w, 16);
                        hp[0] = __floats2half2_rn(vv.x, o0);
                        hp[1] = __floats2half2_rn(vv.y, o1);
                        hp[2] = __floats2half2_rn(vv.z, o2);
                        hp[3] = __floats2half2_rn(vv.w, o3);
                        if (valid && og < 16)
                            *(uint4*)&g_vh2[d * NA64 + gn * 64 + j0] = *(uint4*)hp;
                    }
                }
            }
        }
    }
}

// ---------------- molecule pooling + heads ----------------
__global__ void pool_zero_kernel() {
    int idx = blockIdx.x * blockDim.x + threadIdx.x;
    if (idx < N_MOLS * HID) g_hmol[idx] = 0.f;
    if (idx < N_MOLS) g_cnt[idx] = 0.f;
}

__global__ void pool_acc_kernel(const int* __restrict__ batch) {
    int idx = blockIdx.x * blockDim.x + threadIdx.x;
    if (idx >= NV) return;
    int n = idx >> 7;
    int j = idx & 127;
    int m = batch[n];
    atomicAdd(&g_hmol[m * HID + j], g_s[idx]);
    if (j == 0) atomicAdd(&g_cnt[m], 1.0f);
}

__global__ void head_kernel(const float* __restrict__ lW1, const float* __restrict__ lb1,
                            const float* __restrict__ lW2, const float* __restrict__ lb2,
                            const float* __restrict__ pW1, const float* __restrict__ pb1,
                            const float* __restrict__ pW2, const float* __restrict__ pb2,
                            float* __restrict__ out) {
    __shared__ float hm[HID];
    __shared__ float tt[HID];
    __shared__ float red[HID];
    int m = blockIdx.x;
    int j = threadIdx.x;
    float cnt = g_cnt[m];
    hm[j] = g_hmol[m * HID + j] / cnt;
    __syncthreads();

    float acc = lb1[j];
    for (int k = 0; k < HID; k++) acc += hm[k] * lW1[k * HID + j];
    tt[j] = silu_f(acc);
    __syncthreads();
    red[j] = tt[j] * lW2[j];
    __syncthreads();
    for (int s = 64; s > 0; s >>= 1) {
        if (j < s) red[j] += red[j + s];
        __syncthreads();
    }
    if (j == 0) out[m] = red[0] + lb2[0];
    __syncthreads();

    acc = pb1[j];
    for (int k = 0; k < HID; k++) acc += hm[k] * pW1[k * HID + j];
    tt[j] = silu_f(acc);
    __syncthreads();
    red[j] = tt[j] * pW2[j];
    __syncthreads();
    for (int s = 64; s > 0; s >>= 1) {
        if (j < s) red[j] += red[j + s];
        __syncthreads();
    }
    if (j == 0) {
        float x = red[0] + pb2[0];
        out[N_MOLS + m] = 1.0f / (1.0f + expf(-x));
    }
}

// ---------------- launch ----------------
extern "C" void kernel_launch(void* const* d_in, const int* in_sizes, int n_in,
                              void* d_out, int out_size) {
    const int* z = (const int*)d_in[0];
    const float* pos = (const float*)d_in[1];
    const int* ei = (const int*)d_in[2];
    const int* batch = (const int*)d_in[3];
    const float* emb = (const float*)d_in[4];
    const float* fW1 = (const float*)d_in[5];
    const float* fb1 = (const float*)d_in[6];
    const float* fW2 = (const float*)d_in[7];
    const float* fb2 = (const float*)d_in[8];
    const float* uW1 = (const float*)d_in[9];
    const float* ub1 = (const float*)d_in[10];
    const float* uW2 = (const float*)d_in[11];
    const float* ub2 = (const float*)d_in[12];
    const float* lW1 = (const float*)d_in[13];
    const float* lb1 = (const float*)d_in[14];
    const float* lW2 = (const float*)d_in[15];
    const float* lb2 = (const float*)d_in[16];
    const float* pW1 = (const float*)d_in[17];
    const float* pb1 = (const float*)d_in[18];
    const float* pW2 = (const float*)d_in[19];
    const float* pb2 = (const float*)d_in[20];
    float* out = (float*)d_out;

    cudaFuncSetAttribute(table_kernel, cudaFuncAttributeMaxDynamicSharedMemorySize,
                         TAB_SMEM_FLOATS * 4);
    cudaFuncSetAttribute(node_kernel, cudaFuncAttributeMaxDynamicSharedMemorySize,
                         NODE_SMEM_FLOATS * 4);

    init_kernel<<<(3 * NA64 + 255) / 256, 256>>>(z, emb);

    const int scan_blocks = (N_ATOMS + SCAN_B - 1) / SCAN_B;
    hist_kernel<<<(N_EDGES + 255) / 256, 256>>>(ei);
    scan1_kernel<<<scan_blocks, SCAN_B>>>();
    scan2_kernel<<<1, 32>>>(scan_blocks);
    scan3_kernel<<<(N_ATOMS + 255) / 256, 256>>>();
    scatter_kernel<<<(N_EDGES + 255) / 256, 256>>>(ei, pos);

    table_kernel<<<dim3(TAB_D / 64, NLAYERS), 512, TAB_SMEM_FLOATS * 4>>>(fW1, fb1, fW2, fb2);

    const int msg_blocks = (N_ATOMS * 32 + 255) / 256;
    const int node_blocks = (N_ATOMS + NT - 1) / NT;
    for (int layer = 0; layer < NLAYERS; layer++) {
        msg_kernel<<<msg_blocks, 256>>>(layer);
        node_kernel<<<node_blocks, 256, NODE_SMEM_FLOATS * 4>>>(layer, uW1, ub1, uW2, ub2);
    }

    pool_zero_kernel<<<(N_MOLS * HID + 255) / 256, 256>>>();
    pool_acc_kernel<<<(NV + 255) / 256, 256>>>(batch);
    head_kernel<<<N_MOLS, HID>>>(lW1, lb1, lW2, lb2, pW1, pb1, pW2, pb2, out);
}

// round 9
// speedup vs baseline: 1.8655x; 1.0657x over previous
#include <cuda_runtime.h>
#include <cuda_fp16.h>
#include <math.h>

#define N_ATOMS 50000
#define N_EDGES 400000
#define N_MOLS  500
#define HID     128
#define NRBF    20
#define NLAYERS 4
#define NV      (N_ATOMS * HID)

#define TAB_D   2048
#define TAB_MAX 12.0f
#define RBF_STEP (5.0f / (float)(NRBF - 1))

typedef unsigned long long ull;

// ---------------- device scratch ----------------
__device__ float  g_s[NV];            // fp32 master s
__device__ __half g_sh[NV];           // half mirror of s, plain [n][128]
__device__ __half g_vh[3 * NV];       // half v (sole copy), planar [3][n][128]
__device__ float  g_ms[NV];
__device__ float  g_vn[NV];           // ||m_v|| (fp32, computed pre-rounding)
__device__ __half g_mvh[3 * NV];      // half m_v
__device__ __half2 g_htabh[NLAYERS * TAB_D * 3 * HID]; // [layer][grid][sec][128] endpoint pairs
__device__ float g_hmol[N_MOLS * HID];
__device__ float g_cnt[N_MOLS];

// CSR scratch
__device__ int   g_deg[N_ATOMS];
__device__ int   g_rowptr[N_ATOMS + 1];
__device__ int   g_cursor[N_ATOMS];
__device__ int   g_bsum[128];
__device__ int   g_ecol[N_EDGES];
__device__ float4 g_egeo[N_EDGES];    // (dirx, diry, dirz, dist*INV_DELTA)

__device__ __forceinline__ float silu_f(float x) { return x / (1.0f + expf(-x)); }

__device__ __forceinline__ ull pack2(float lo, float hi) {
    ull r;
    asm("mov.b64 %0, {%1, %2};" : "=l"(r) : "f"(lo), "f"(hi));
    return r;
}
__device__ __forceinline__ void unpack2(ull v, float& lo, float& hi) {
    asm("mov.b64 {%0, %1}, %2;" : "=f"(lo), "=f"(hi) : "l"(v));
}
#define FMA_F32X2(acc, a, b) \
    asm("fma.rn.f32x2 %0, %1, %2, %0;" : "+l"(acc) : "l"(a), "l"(b))

__device__ __forceinline__ float4 h4_to_f4(uint2 u) {
    __half2 h01 = *(__half2*)&u.x;
    __half2 h23 = *(__half2*)&u.y;
    float2 a = __half22float2(h01);
    float2 b = __half22float2(h23);
    return make_float4(a.x, a.y, b.x, b.y);
}
__device__ __forceinline__ uint2 f4_to_h4(float x, float y, float z, float w) {
    __half2 h01 = __floats2half2_rn(x, y);
    __half2 h23 = __floats2half2_rn(z, w);
    uint2 r;
    r.x = *(unsigned*)&h01;
    r.y = *(unsigned*)&h23;
    return r;
}

// ---------------- init ----------------
__global__ void init_kernel(const int* __restrict__ z, const float* __restrict__ emb) {
    int idx = blockIdx.x * blockDim.x + threadIdx.x;
    if (idx < N_ATOMS) g_deg[idx] = 0;
    if (idx >= NV) return;
    int n = idx >> 7;
    int j = idx & 127;
    float s = emb[z[n] * HID + j];
    g_s[idx] = s;
    g_sh[idx] = __float2half(s);
}

// ---------------- CSR build ----------------
__global__ void hist_kernel(const int* __restrict__ ei) {
    int e = blockIdx.x * blockDim.x + threadIdx.x;
    if (e >= N_EDGES) return;
    atomicAdd(&g_deg[ei[e]], 1);
}

#define SCAN_B 512
__global__ void scan1_kernel() {
    __shared__ int s[SCAN_B];
    int t = threadIdx.x;
    int i = blockIdx.x * SCAN_B + t;
    int v = (i < N_ATOMS) ? g_deg[i] : 0;
    s[t] = v;
    __syncthreads();
    for (int off = 1; off < SCAN_B; off <<= 1) {
        int add = (t >= off) ? s[t - off] : 0;
        __syncthreads();
        s[t] += add;
        __syncthreads();
    }
    if (i < N_ATOMS) g_rowptr[i] = s[t] - v;
    if (t == SCAN_B - 1) g_bsum[blockIdx.x] = s[t];
}

__global__ void scan2_kernel(int nblocks) {
    if (threadIdx.x == 0) {
        int run = 0;
        for (int b = 0; b < nblocks; b++) {
            int t = g_bsum[b];
            g_bsum[b] = run;
            run += t;
        }
    }
}

__global__ void scan3_kernel() {
    int i = blockIdx.x * blockDim.x + threadIdx.x;
    if (i < N_ATOMS) {
        int rp = g_rowptr[i] + g_bsum[i >> 9];
        g_rowptr[i] = rp;
        g_cursor[i] = rp;
    }
    if (i == 0) g_rowptr[N_ATOMS] = N_EDGES;
}

__global__ void scatter_kernel(const int* __restrict__ ei, const float* __restrict__ pos) {
    int e = blockIdx.x * blockDim.x + threadIdx.x;
    if (e >= N_EDGES) return;
    int r = ei[e];
    int c = ei[N_EDGES + e];
    float dx = pos[c * 3 + 0] - pos[r * 3 + 0];
    float dy = pos[c * 3 + 1] - pos[r * 3 + 1];
    float dz = pos[c * 3 + 2] - pos[r * 3 + 2];
    float dist = sqrtf(dx * dx + dy * dy + dz * dz);
    float inv = 1.0f / (dist + 1e-8f);
    const float INV_DELTA = (float)(TAB_D - 1) / TAB_MAX;
    int p = atomicAdd(&g_cursor[r], 1);
    g_ecol[p] = c;
    g_egeo[p] = make_float4(dx * inv, dy * inv, dz * inv, dist * INV_DELTA);
}

// ---------------- filter table build (fp32 math, half2 endpoint store) ----------------
#define TAB_SMEM_FLOATS 20736

extern "C" __global__ void __launch_bounds__(512, 1)
table_kernel(const float* __restrict__ fW1, const float* __restrict__ fb1,
             const float* __restrict__ fW2, const float* __restrict__ fb2) {
    extern __shared__ float sm[];
    float* hid = sm;                 // [64][132]
    float* rbf_s = sm + 8448;        // [64][20]
    float* w1_s = sm + 9728;         // [20][128]
    float* w2_s = sm + 8448;         // [32][384] (stage2, overlaps)

    const int tid = threadIdx.x;
    const int layer = blockIdx.y;
    const int g0 = blockIdx.x * 64;
    const float* W1 = fW1 + layer * NRBF * HID;
    const float* b1 = fb1 + layer * HID;
    const float* W2 = fW2 + layer * HID * 3 * HID;
    const float* b2 = fb2 + layer * 3 * HID;
    const float DELTA = TAB_MAX / (float)(TAB_D - 1);

    for (int idx = tid; idx < 64 * NRBF; idx += 512) {
        int e = idx / NRBF, k = idx % NRBF;
        float d = (float)(g0 + e) * DELTA - RBF_STEP * (float)k;
        rbf_s[idx] = expf(-d * d);
    }
    for (int idx = tid; idx < NRBF * HID; idx += 512) w1_s[idx] = W1[idx];
    __syncthreads();

    const int jg = tid & 31;
    const int eg = tid >> 5;
    const int j0 = jg * 4;
    const int el0 = eg * 4;

    float hacc[4][4];
#pragma unroll
    for (int a = 0; a < 4; a++)
#pragma unroll
        for (int b = 0; b < 4; b++) hacc[a][b] = b1[j0 + b];
#pragma unroll
    for (int k = 0; k < NRBF; k++) {
        float r[4];
#pragma unroll
        for (int a = 0; a < 4; a++) r[a] = rbf_s[(el0 + a) * NRBF + k];
        float4 w = *(const float4*)&w1_s[k * HID + j0];
        float wv[4] = {w.x, w.y, w.z, w.w};
#pragma unroll
        for (int a = 0; a < 4; a++)
#pragma unroll
            for (int b = 0; b < 4; b++) hacc[a][b] += r[a] * wv[b];
    }
#pragma unroll
    for (int a = 0; a < 4; a++)
#pragma unroll
        for (int b = 0; b < 4; b++) hid[(el0 + a) * 132 + j0 + b] = silu_f(hacc[a][b]);
    __syncthreads();

    float a_ss[4][4], a_vv[4][4], a_sv[4][4];
#pragma unroll
    for (int a = 0; a < 4; a++)
#pragma unroll
        for (int b = 0; b < 4; b++) { a_ss[a][b] = 0.f; a_vv[a][b] = 0.f; a_sv[a][b] = 0.f; }

    for (int kc = 0; kc < HID; kc += 32) {
        __syncthreads();
        for (int idx = tid; idx < 32 * 384; idx += 512) w2_s[idx] = W2[kc * 384 + idx];
        __syncthreads();
#pragma unroll 8
        for (int kk = 0; kk < 32; kk++) {
            float h[4];
#pragma unroll
            for (int a = 0; a < 4; a++) h[a] = hid[(el0 + a) * 132 + kc + kk];
            float4 wss = *(const float4*)&w2_s[kk * 384 + j0];
            float4 wvv = *(const float4*)&w2_s[kk * 384 + 128 + j0];
            float4 wsv = *(const float4*)&w2_s[kk * 384 + 256 + j0];
            float ss[4] = {wss.x, wss.y, wss.z, wss.w};
            float vv[4] = {wvv.x, wvv.y, wvv.z, wvv.w};
            float sv[4] = {wsv.x, wsv.y, wsv.z, wsv.w};
#pragma unroll
            for (int a = 0; a < 4; a++)
#pragma unroll
                for (int b = 0; b < 4; b++) {
                    a_ss[a][b] += h[a] * ss[b];
                    a_vv[a][b] += h[a] * vv[b];
                    a_sv[a][b] += h[a] * sv[b];
                }
        }
    }

    // layout: [grid][sec][128] half2; .x = h(gi), .y of entry gi-1 = h(gi)
#pragma unroll
    for (int a = 0; a < 4; a++) {
        int gi = g0 + el0 + a;
        __half* Tx = (__half*)(g_htabh + ((size_t)layer * TAB_D + gi) * 384);
        __half* Ty = (__half*)(g_htabh + ((size_t)layer * TAB_D + gi - 1) * 384);
#pragma unroll
        for (int b = 0; b < 4; b++) {
            int ch = j0 + b;
            float hss = a_ss[a][b] + b2[ch];
            float hvv = a_vv[a][b] + b2[128 + ch];
            float hsv = a_sv[a][b] + b2[256 + ch];
            Tx[(0 * 128 + ch) * 2] = __float2half(hss);
            Tx[(1 * 128 + ch) * 2] = __float2half(hvv);
            Tx[(2 * 128 + ch) * 2] = __float2half(hsv);
            if (gi > 0) {
                Ty[(0 * 128 + ch) * 2 + 1] = __float2half(hss);
                Ty[(1 * 128 + ch) * 2 + 1] = __float2half(hvv);
                Ty[(2 * 128 + ch) * 2 + 1] = __float2half(hsv);
            }
        }
    }
}

// ---------------- edge message kernel: CSR segment-sum, warp per row ----------------
// blocked channels: lane owns j = lane*4 .. lane*4+3; fully vectorized, value-pipelined
extern "C" __global__ void __launch_bounds__(256)
msg_kernel(int layer) {
    int r = (blockIdx.x * 256 + threadIdx.x) >> 5;
    int lane = threadIdx.x & 31;
    if (r >= N_ATOMS) return;

    int beg = g_rowptr[r];
    int end = g_rowptr[r + 1];
    int base = r * HID + lane * 4;

    if (beg >= end) {
        *(float4*)&g_ms[base] = make_float4(0.f, 0.f, 0.f, 0.f);
        *(float4*)&g_vn[base] = make_float4(0.f, 0.f, 0.f, 0.f);
        uint2 z; z.x = 0u; z.y = 0u;
        *(uint2*)&g_mvh[0 * NV + base] = z;
        *(uint2*)&g_mvh[1 * NV + base] = z;
        *(uint2*)&g_mvh[2 * NV + base] = z;
        return;
    }

    const bool hasv = (layer != 0);
    const __half2* Tl = g_htabh + (size_t)layer * TAB_D * 384;

    float accS[4] = {0.f, 0.f, 0.f, 0.f};
    float accV[12];
#pragma unroll
    for (int q = 0; q < 12; q++) accV[q] = 0.f;

    // prime pipeline
    int colN = __ldg(&g_ecol[beg]);
    float4 geoN = __ldg(&g_egeo[beg]);
    float fN;
    const uint4* TbN;
    {
        float u = geoN.w;
        int i0 = (int)u;
        if (i0 > TAB_D - 2) i0 = TAB_D - 2;
        fN = fminf(u - (float)i0, 1.0f);
        TbN = (const uint4*)(Tl + (size_t)i0 * 384);
    }
    uint4 t0N = __ldcg(&TbN[lane]);
    uint4 t1N = __ldcg(&TbN[32 + lane]);
    uint4 t2N = __ldcg(&TbN[64 + lane]);
    uint2 sN = __ldcg((const uint2*)&g_sh[colN * HID + lane * 4]);
    uint2 v0N, v1N, v2N;
    v0N.x = v0N.y = v1N.x = v1N.y = v2N.x = v2N.y = 0u;
    if (hasv) {
        v0N = __ldcg((const uint2*)&g_vh[0 * NV + colN * HID + lane * 4]);
        v1N = __ldcg((const uint2*)&g_vh[1 * NV + colN * HID + lane * 4]);
        v2N = __ldcg((const uint2*)&g_vh[2 * NV + colN * HID + lane * 4]);
    }

    for (int p = beg; p < end; p++) {
        float4 geo = geoN;
        float f = fN;
        uint4 t0 = t0N, t1 = t1N, t2 = t2N;
        uint2 sv = sN, v0 = v0N, v1 = v1N, v2 = v2N;

        if (p + 1 < end) {
            colN = __ldg(&g_ecol[p + 1]);
            geoN = __ldg(&g_egeo[p + 1]);
            float u = geoN.w;
            int i0 = (int)u;
            if (i0 > TAB_D - 2) i0 = TAB_D - 2;
            fN = fminf(u - (float)i0, 1.0f);
            TbN = (const uint4*)(Tl + (size_t)i0 * 384);
            t0N = __ldcg(&TbN[lane]);
            t1N = __ldcg(&TbN[32 + lane]);
            t2N = __ldcg(&TbN[64 + lane]);
            sN = __ldcg((const uint2*)&g_sh[colN * HID + lane * 4]);
            if (hasv) {
                v0N = __ldcg((const uint2*)&g_vh[0 * NV + colN * HID + lane * 4]);
                v1N = __ldcg((const uint2*)&g_vh[1 * NV + colN * HID + lane * 4]);
                v2N = __ldcg((const uint2*)&g_vh[2 * NV + colN * HID + lane * 4]);
            }
        }

        float4 scf = h4_to_f4(sv);
        float sc[4] = {scf.x, scf.y, scf.z, scf.w};
        float vc0[4], vc1[4], vc2[4];
        if (hasv) {
            float4 a0 = h4_to_f4(v0);
            float4 a1 = h4_to_f4(v1);
            float4 a2 = h4_to_f4(v2);
            vc0[0] = a0.x; vc0[1] = a0.y; vc0[2] = a0.z; vc0[3] = a0.w;
            vc1[0] = a1.x; vc1[1] = a1.y; vc1[2] = a1.z; vc1[3] = a1.w;
            vc2[0] = a2.x; vc2[1] = a2.y; vc2[2] = a2.z; vc2[3] = a2.w;
        }

        const __half2* e0 = (const __half2*)&t0;
        const __half2* e1 = (const __half2*)&t1;
        const __half2* e2 = (const __half2*)&t2;
#pragma unroll
        for (int c = 0; c < 4; c++) {
            float2 pss = __half22float2(e0[c]);
            float2 pvv = __half22float2(e1[c]);
            float2 psv = __half22float2(e2[c]);
            float hss = pss.x + f * (pss.y - pss.x);
            float hvv = pvv.x + f * (pvv.y - pvv.x);
            float hsv = psv.x + f * (psv.y - psv.x);
            accS[c] += hss * sc[c];
            float cc = hsv * sc[c];
            if (hasv) {
                accV[c]     += hvv * vc0[c] + cc * geo.x;
                accV[4 + c] += hvv * vc1[c] + cc * geo.y;
                accV[8 + c] += hvv * vc2[c] + cc * geo.z;
            } else {
                accV[c]     += cc * geo.x;
                accV[4 + c] += cc * geo.y;
                accV[8 + c] += cc * geo.z;
            }
        }
    }

    *(float4*)&g_ms[base] = make_float4(accS[0], accS[1], accS[2], accS[3]);
    float vn[4];
#pragma unroll
    for (int c = 0; c < 4; c++)
        vn[c] = sqrtf(accV[c] * accV[c] + accV[4 + c] * accV[4 + c] + accV[8 + c] * accV[8 + c]);
    *(float4*)&g_vn[base] = make_float4(vn[0], vn[1], vn[2], vn[3]);
    *(uint2*)&g_mvh[0 * NV + base] = f4_to_h4(accV[0], accV[1], accV[2], accV[3]);
    *(uint2*)&g_mvh[1 * NV + base] = f4_to_h4(accV[4], accV[5], accV[6], accV[7]);
    *(uint2*)&g_mvh[2 * NV + base] = f4_to_h4(accV[8], accV[9], accV[10], accV[11]);
}

// ---------------- node update kernel (f32x2 FMA, reg-prefetched x and W, half v) ----------------
#define NT 64
#define XS_STRIDE 76
#define NODE_SMEM_FLOATS 22784

extern "C" __global__ void __launch_bounds__(256, 2)
node_kernel(int layer,
            const float* __restrict__ uW1, const float* __restrict__ ub1,
            const float* __restrict__ uW2, const float* __restrict__ ub2) {
    extern __shared__ float sm[];
    float* xs_t = sm;              // [64 k][76]  (stage1); alpha half buf in stage2
    float* wc   = sm + 4864;       // [64 k][128]
    float* ts_t = sm + 13056;      // [128 k][76]
    __half* alpha_s = (__half*)sm; // [64 node][128 ch] halves = 16KB (inside xs_t region)

    const int tid = threadIdx.x;
    const int n0 = blockIdx.x * NT;
    const float* W1 = uW1 + layer * 384 * HID;
    const float* b1 = ub1 + layer * HID;
    const float* W2 = uW2 + layer * HID * 384;
    const float* b2 = ub2 + layer * 384;

    const int og = tid & 31;
    const int ng = tid >> 5;
    const int j0 = og * 4;
    const int nl0 = ng * 8;

    // xs staging mapping: thread -> (node, 4 k-quads)
    const int snode = tid & 63;
    const int sq = (tid >> 6) << 2;          // 0,4,8,12
    const int sgn = n0 + snode;
    const bool svalid = (sgn < N_ATOMS);

    float4 wreg[8];
#pragma unroll
    for (int q = 0; q < 8; q++) {
        int idx = q * 256 + tid;
        int k = idx >> 5, c4 = idx & 31;
        wreg[q] = *(const float4*)&W1[k * HID + c4 * 4];
    }

    float4 xpre[4];
    {
        const float* sp = g_s + (size_t)sgn * HID;   // chunk 0: g_s
#pragma unroll
        for (int q = 0; q < 4; q++)
            xpre[q] = svalid ? *(const float4*)&sp[sq + 16 * q]
                             : make_float4(0.f, 0.f, 0.f, 0.f);
    }

    // ---- stage 1: t = silu(x @ W1 + b1) ----
    float4 b1v = *(const float4*)&b1[j0];
    ull accP[4][4];
    {
        float bb[4] = {b1v.x, b1v.y, b1v.z, b1v.w};
#pragma unroll
        for (int ap = 0; ap < 4; ap++)
#pragma unroll
            for (int b = 0; b < 4; b++) accP[ap][b] = pack2(bb[b], bb[b]);
    }

    for (int kc = 0; kc < 384; kc += 64) {
        __syncthreads();
#pragma unroll
        for (int q = 0; q < 8; q++) {
            int idx = q * 256 + tid;
            int k = idx >> 5, c4 = idx & 31;
            *(float4*)&wc[k * 128 + c4 * 4] = wreg[q];
        }
#pragma unroll
        for (int q = 0; q < 4; q++) {
            int kl = sq + 16 * q;
            xs_t[(kl + 0) * XS_STRIDE + snode] = xpre[q].x;
            xs_t[(kl + 1) * XS_STRIDE + snode] = xpre[q].y;
            xs_t[(kl + 2) * XS_STRIDE + snode] = xpre[q].z;
            xs_t[(kl + 3) * XS_STRIDE + snode] = xpre[q].w;
        }
        __syncthreads();
        if (kc + 64 < 384) {
            int nkc = kc + 64;
            const float* src = (nkc < 128) ? g_s : ((nkc < 256) ? g_ms : g_vn);
            const float* sp = src + (size_t)sgn * HID + (nkc & 127);
#pragma unroll
            for (int q = 0; q < 8; q++) {
                int idx = q * 256 + tid;
                int k = idx >> 5, c4 = idx & 31;
                wreg[q] = *(const float4*)&W1[(nkc + k) * HID + c4 * 4];
            }
#pragma unroll
            for (int q = 0; q < 4; q++)
                xpre[q] = svalid ? *(const float4*)&sp[sq + 16 * q]
                                 : make_float4(0.f, 0.f, 0.f, 0.f);
        } else {
#pragma unroll
            for (int q = 0; q < 8; q++) {
                int idx = q * 256 + tid;
                int k = idx >> 5, c4 = idx & 31;
                wreg[q] = *(const float4*)&W2[k * 384 + c4 * 4];
            }
        }
#pragma unroll 4
        for (int kk = 0; kk < 64; kk++) {
            const ull* ax = (const ull*)&xs_t[kk * XS_STRIDE + nl0];
            ull a0 = ax[0], a1 = ax[1], a2 = ax[2], a3 = ax[3];
            float4 w = *(const float4*)&wc[kk * 128 + j0];
            ull w0 = pack2(w.x, w.x), w1 = pack2(w.y, w.y);
            ull w2 = pack2(w.z, w.z), w3 = pack2(w.w, w.w);
            FMA_F32X2(accP[0][0], a0, w0); FMA_F32X2(accP[1][0], a1, w0);
            FMA_F32X2(accP[2][0], a2, w0); FMA_F32X2(accP[3][0], a3, w0);
            FMA_F32X2(accP[0][1], a0, w1); FMA_F32X2(accP[1][1], a1, w1);
            FMA_F32X2(accP[2][1], a2, w1); FMA_F32X2(accP[3][1], a3, w1);
            FMA_F32X2(accP[0][2], a0, w2); FMA_F32X2(accP[1][2], a1, w2);
            FMA_F32X2(accP[2][2], a2, w2); FMA_F32X2(accP[3][2], a3, w2);
            FMA_F32X2(accP[0][3], a0, w3); FMA_F32X2(accP[1][3], a1, w3);
            FMA_F32X2(accP[2][3], a2, w3); FMA_F32X2(accP[3][3], a3, w3);
        }
    }
#pragma unroll
    for (int ap = 0; ap < 4; ap++)
#pragma unroll
        for (int b = 0; b < 4; b++) {
            float lo, hi;
            unpack2(accP[ap][b], lo, hi);
            ts_t[(j0 + b) * XS_STRIDE + nl0 + 2 * ap] = silu_f(lo);
            ts_t[(j0 + b) * XS_STRIDE + nl0 + 2 * ap + 1] = silu_f(hi);
        }

    // ---- stage 2: u = t @ W2 + b2; jb0=delta_s, jb1=alpha (to smem), jb2=beta+v update ----
    ull u2P[4][4];
    for (int c = 0; c < 6; c++) {
        int jb = c >> 1;
        int kc2 = (c & 1) * 64;
        if (kc2 == 0) {
#pragma unroll
            for (int ap = 0; ap < 4; ap++)
#pragma unroll
                for (int b = 0; b < 4; b++) u2P[ap][b] = 0ull;
        }
        __syncthreads();
#pragma unroll
        for (int q = 0; q < 8; q++) {
            int idx = q * 256 + tid;
            int k = idx >> 5, c4 = idx & 31;
            *(float4*)&wc[k * 128 + c4 * 4] = wreg[q];
        }
        __syncthreads();
        if (c < 5) {
            int cn = c + 1;
            int jbn = cn >> 1;
            int kc2n = (cn & 1) * 64;
#pragma unroll
            for (int q = 0; q < 8; q++) {
                int idx = q * 256 + tid;
                int k = idx >> 5, c4 = idx & 31;
                wreg[q] = *(const float4*)&W2[(kc2n + k) * 384 + jbn * 128 + c4 * 4];
            }
        }
#pragma unroll 4
        for (int kk = 0; kk < 64; kk++) {
            const ull* ax = (const ull*)&ts_t[(kc2 + kk) * XS_STRIDE + nl0];
            ull a0 = ax[0], a1 = ax[1], a2 = ax[2], a3 = ax[3];
            float4 w = *(const float4*)&wc[kk * 128 + j0];
            ull w0 = pack2(w.x, w.x), w1 = pack2(w.y, w.y);
            ull w2 = pack2(w.z, w.z), w3 = pack2(w.w, w.w);
            FMA_F32X2(u2P[0][0], a0, w0); FMA_F32X2(u2P[1][0], a1, w0);
            FMA_F32X2(u2P[2][0], a2, w0); FMA_F32X2(u2P[3][0], a3, w0);
            FMA_F32X2(u2P[0][1], a0, w1); FMA_F32X2(u2P[1][1], a1, w1);
            FMA_F32X2(u2P[2][1], a2, w1); FMA_F32X2(u2P[3][1], a3, w1);
            FMA_F32X2(u2P[0][2], a0, w2); FMA_F32X2(u2P[1][2], a1, w2);
            FMA_F32X2(u2P[2][2], a2, w2); FMA_F32X2(u2P[3][2], a3, w2);
            FMA_F32X2(u2P[0][3], a0, w3); FMA_F32X2(u2P[1][3], a1, w3);
            FMA_F32X2(u2P[2][3], a2, w3); FMA_F32X2(u2P[3][3], a3, w3);
        }

        if (kc2 == 64) {
            float u2[8][4];
#pragma unroll
            for (int ap = 0; ap < 4; ap++)
#pragma unroll
                for (int b = 0; b < 4; b++)
                    unpack2(u2P[ap][b], u2[2 * ap][b], u2[2 * ap + 1][b]);

            float4 b2v = *(const float4*)&b2[jb * 128 + j0];
            float bb[4] = {b2v.x, b2v.y, b2v.z, b2v.w};
#pragma unroll
            for (int a = 0; a < 8; a++) {
                int gn = n0 + nl0 + a;
                if (gn >= N_ATOMS) continue;
                if (jb == 0) {
                    float sn[4];
#pragma unroll
                    for (int b = 0; b < 4; b++) {
                        sn[b] = g_s[gn * HID + j0 + b] + u2[a][b] + bb[b];
                        g_s[gn * HID + j0 + b] = sn[b];
                    }
                    *(uint2*)&g_sh[gn * HID + j0] = f4_to_h4(sn[0], sn[1], sn[2], sn[3]);
                } else if (jb == 1) {
                    *(uint2*)&alpha_s[(nl0 + a) * 128 + j0] =
                        f4_to_h4(u2[a][0] + bb[0], u2[a][1] + bb[1],
                                 u2[a][2] + bb[2], u2[a][3] + bb[3]);
                } else {
                    float4 al = h4_to_f4(*(const uint2*)&alpha_s[(nl0 + a) * 128 + j0]);
                    float alv[4] = {al.x, al.y, al.z, al.w};
#pragma unroll
                    for (int d = 0; d < 3; d++) {
                        float4 mvf = h4_to_f4(*(const uint2*)&g_mvh[d * NV + gn * HID + j0]);
                        float4 vof = make_float4(0.f, 0.f, 0.f, 0.f);
                        if (layer != 0)
                            vof = h4_to_f4(*(const uint2*)&g_vh[d * NV + gn * HID + j0]);
                        float nx = alv[0] * vof.x + (u2[a][0] + bb[0]) * mvf.x;
                        float ny = alv[1] * vof.y + (u2[a][1] + bb[1]) * mvf.y;
                        float nz = alv[2] * vof.z + (u2[a][2] + bb[2]) * mvf.z;
                        float nw = alv[3] * vof.w + (u2[a][3] + bb[3]) * mvf.w;
                        *(uint2*)&g_vh[d * NV + gn * HID + j0] = f4_to_h4(nx, ny, nz, nw);
                    }
                }
            }
        }
    }
}

// ---------------- molecule pooling + heads ----------------
__global__ void pool_zero_kernel() {
    int idx = blockIdx.x * blockDim.x + threadIdx.x;
    if (idx < N_MOLS * HID) g_hmol[idx] = 0.f;
    if (idx < N_MOLS) g_cnt[idx] = 0.f;
}

__global__ void pool_acc_kernel(const int* __restrict__ batch) {
    int idx = blockIdx.x * blockDim.x + threadIdx.x;
    if (idx >= NV) return;
    int n = idx >> 7;
    int j = idx & 127;
    int m = batch[n];
    atomicAdd(&g_hmol[m * HID + j], g_s[idx]);
    if (j == 0) atomicAdd(&g_cnt[m], 1.0f);
}

__global__ void head_kernel(const float* __restrict__ lW1, const float* __restrict__ lb1,
                            const float* __restrict__ lW2, const float* __restrict__ lb2,
                            const float* __restrict__ pW1, const float* __restrict__ pb1,
                            const float* __restrict__ pW2, const float* __restrict__ pb2,
                            float* __restrict__ out) {
    __shared__ float hm[HID];
    __shared__ float tt[HID];
    __shared__ float red[HID];
    int m = blockIdx.x;
    int j = threadIdx.x;
    float cnt = g_cnt[m];
    hm[j] = g_hmol[m * HID + j] / cnt;
    __syncthreads();

    float acc = lb1[j];
    for (int k = 0; k < HID; k++) acc += hm[k] * lW1[k * HID + j];
    tt[j] = silu_f(acc);
    __syncthreads();
    red[j] = tt[j] * lW2[j];
    __syncthreads();
    for (int s = 64; s > 0; s >>= 1) {
        if (j < s) red[j] += red[j + s];
        __syncthreads();
    }
    if (j == 0) out[m] = red[0] + lb2[0];
    __syncthreads();

    acc = pb1[j];
    for (int k = 0; k < HID; k++) acc += hm[k] * pW1[k * HID + j];
    tt[j] = silu_f(acc);
    __syncthreads();
    red[j] = tt[j] * pW2[j];
    __syncthreads();
    for (int s = 64; s > 0; s >>= 1) {
        if (j < s) red[j] += red[j + s];
        __syncthreads();
    }
    if (j == 0) {
        float x = red[0] + pb2[0];
        out[N_MOLS + m] = 1.0f / (1.0f + expf(-x));
    }
}

// ---------------- launch ----------------
extern "C" void kernel_launch(void* const* d_in, const int* in_sizes, int n_in,
                              void* d_out, int out_size) {
    const int* z = (const int*)d_in[0];
    const float* pos = (const float*)d_in[1];
    const int* ei = (const int*)d_in[2];
    const int* batch = (const int*)d_in[3];
    const float* emb = (const float*)d_in[4];
    const float* fW1 = (const float*)d_in[5];
    const float* fb1 = (const float*)d_in[6];
    const float* fW2 = (const float*)d_in[7];
    const float* fb2 = (const float*)d_in[8];
    const float* uW1 = (const float*)d_in[9];
    const float* ub1 = (const float*)d_in[10];
    const float* uW2 = (const float*)d_in[11];
    const float* ub2 = (const float*)d_in[12];
    const float* lW1 = (const float*)d_in[13];
    const float* lb1 = (const float*)d_in[14];
    const float* lW2 = (const float*)d_in[15];
    const float* lb2 = (const float*)d_in[16];
    const float* pW1 = (const float*)d_in[17];
    const float* pb1 = (const float*)d_in[18];
    const float* pW2 = (const float*)d_in[19];
    const float* pb2 = (const float*)d_in[20];
    float* out = (float*)d_out;

    cudaFuncSetAttribute(table_kernel, cudaFuncAttributeMaxDynamicSharedMemorySize,
                         TAB_SMEM_FLOATS * 4);
    cudaFuncSetAttribute(node_kernel, cudaFuncAttributeMaxDynamicSharedMemorySize,
                         NODE_SMEM_FLOATS * 4);

    init_kernel<<<(NV + 255) / 256, 256>>>(z, emb);

    const int scan_blocks = (N_ATOMS + SCAN_B - 1) / SCAN_B;
    hist_kernel<<<(N_EDGES + 255) / 256, 256>>>(ei);
    scan1_kernel<<<scan_blocks, SCAN_B>>>();
    scan2_kernel<<<1, 32>>>(scan_blocks);
    scan3_kernel<<<(N_ATOMS + 255) / 256, 256>>>();
    scatter_kernel<<<(N_EDGES + 255) / 256, 256>>>(ei, pos);

    table_kernel<<<dim3(TAB_D / 64, NLAYERS), 512, TAB_SMEM_FLOATS * 4>>>(fW1, fb1, fW2, fb2);

    const int msg_blocks = (N_ATOMS * 32 + 255) / 256;
    const int node_blocks = (N_ATOMS + NT - 1) / NT;
    for (int layer = 0; layer < NLAYERS; layer++) {
        msg_kernel<<<msg_blocks, 256>>>(layer);
        node_kernel<<<node_blocks, 256, NODE_SMEM_FLOATS * 4>>>(layer, uW1, ub1, uW2, ub2);
    }

    pool_zero_kernel<<<(N_MOLS * HID + 255) / 256, 256>>>();
    pool_acc_kernel<<<(NV + 255) / 256, 256>>>(batch);
    head_kernel<<<N_MOLS, HID>>>(lW1, lb1, lW2, lb2, pW1, pb1, pW2, pb2, out);
}

// round 10
// speedup vs baseline: 2.2203x; 1.1902x over previous
#include <cuda_runtime.h>
#include <cuda_fp16.h>
#include <math.h>

#define N_ATOMS 50000
#define N_EDGES 400000
#define N_MOLS  500
#define HID     128
#define NRBF    20
#define NLAYERS 4
#define NV      (N_ATOMS * HID)

#define TAB_D   2048
#define TAB_MAX 12.0f
#define RBF_STEP (5.0f / (float)(NRBF - 1))

typedef unsigned long long ull;
typedef unsigned int uint;

// ---------------- device scratch ----------------
__device__ float  g_s[NV];            // fp32 master s
__device__ __half g_sh[NV];           // half mirror of s
__device__ __half g_vh[3 * NV];       // half v (sole copy), planar
__device__ float  g_ms[NV];
__device__ float  g_vn[NV];           // ||m_v|| fp32 (pre-rounding)
__device__ __half g_mvh[3 * NV];      // half m_v
__device__ __half2 g_htabh[NLAYERS * TAB_D * 3 * HID];
__device__ float g_hmol[N_MOLS * HID];
__device__ float g_cnt[N_MOLS];

// CSR scratch
__device__ int   g_deg[N_ATOMS];
__device__ int   g_rowptr[N_ATOMS + 1];
__device__ int   g_cursor[N_ATOMS];
__device__ int   g_bsum[128];
__device__ int   g_ecol[N_EDGES];
__device__ float4 g_egeo[N_EDGES];    // (dirx, diry, dirz, dist*INV_DELTA)

__device__ __forceinline__ float silu_f(float x) { return x / (1.0f + expf(-x)); }

__device__ __forceinline__ uint f2tf32(float x) {
    uint r;
    asm("cvt.rna.tf32.f32 %0, %1;" : "=r"(r) : "f"(x));
    return r;
}
__device__ __forceinline__ float tf32f(float x) { return __uint_as_float(f2tf32(x)); }

__device__ __forceinline__ void mma_tf32(float* c, uint a0, uint a1, uint a2, uint a3,
                                         uint b0, uint b1) {
    asm("mma.sync.aligned.m16n8k8.row.col.f32.tf32.tf32.f32 "
        "{%0,%1,%2,%3},{%4,%5,%6,%7},{%8,%9},{%0,%1,%2,%3};"
        : "+f"(c[0]), "+f"(c[1]), "+f"(c[2]), "+f"(c[3])
        : "r"(a0), "r"(a1), "r"(a2), "r"(a3), "r"(b0), "r"(b1));
}

__device__ __forceinline__ float4 h4_to_f4(uint2 u) {
    __half2 h01 = *(__half2*)&u.x;
    __half2 h23 = *(__half2*)&u.y;
    float2 a = __half22float2(h01);
    float2 b = __half22float2(h23);
    return make_float4(a.x, a.y, b.x, b.y);
}
__device__ __forceinline__ uint2 f4_to_h4(float x, float y, float z, float w) {
    __half2 h01 = __floats2half2_rn(x, y);
    __half2 h23 = __floats2half2_rn(z, w);
    uint2 r;
    r.x = *(unsigned*)&h01;
    r.y = *(unsigned*)&h23;
    return r;
}

// ---------------- init ----------------
__global__ void init_kernel(const int* __restrict__ z, const float* __restrict__ emb) {
    int idx = blockIdx.x * blockDim.x + threadIdx.x;
    if (idx < N_ATOMS) g_deg[idx] = 0;
    if (idx >= NV) return;
    int n = idx >> 7;
    int j = idx & 127;
    float s = emb[z[n] * HID + j];
    g_s[idx] = s;
    g_sh[idx] = __float2half(s);
}

// ---------------- CSR build ----------------
__global__ void hist_kernel(const int* __restrict__ ei) {
    int e = blockIdx.x * blockDim.x + threadIdx.x;
    if (e >= N_EDGES) return;
    atomicAdd(&g_deg[ei[e]], 1);
}

#define SCAN_B 512
__global__ void scan1_kernel() {
    __shared__ int s[SCAN_B];
    int t = threadIdx.x;
    int i = blockIdx.x * SCAN_B + t;
    int v = (i < N_ATOMS) ? g_deg[i] : 0;
    s[t] = v;
    __syncthreads();
    for (int off = 1; off < SCAN_B; off <<= 1) {
        int add = (t >= off) ? s[t - off] : 0;
        __syncthreads();
        s[t] += add;
        __syncthreads();
    }
    if (i < N_ATOMS) g_rowptr[i] = s[t] - v;
    if (t == SCAN_B - 1) g_bsum[blockIdx.x] = s[t];
}

__global__ void scan2_kernel(int nblocks) {
    if (threadIdx.x == 0) {
        int run = 0;
        for (int b = 0; b < nblocks; b++) {
            int t = g_bsum[b];
            g_bsum[b] = run;
            run += t;
        }
    }
}

__global__ void scan3_kernel() {
    int i = blockIdx.x * blockDim.x + threadIdx.x;
    if (i < N_ATOMS) {
        int rp = g_rowptr[i] + g_bsum[i >> 9];
        g_rowptr[i] = rp;
        g_cursor[i] = rp;
    }
    if (i == 0) g_rowptr[N_ATOMS] = N_EDGES;
}

__global__ void scatter_kernel(const int* __restrict__ ei, const float* __restrict__ pos) {
    int e = blockIdx.x * blockDim.x + threadIdx.x;
    if (e >= N_EDGES) return;
    int r = ei[e];
    int c = ei[N_EDGES + e];
    float dx = pos[c * 3 + 0] - pos[r * 3 + 0];
    float dy = pos[c * 3 + 1] - pos[r * 3 + 1];
    float dz = pos[c * 3 + 2] - pos[r * 3 + 2];
    float dist = sqrtf(dx * dx + dy * dy + dz * dz);
    float inv = 1.0f / (dist + 1e-8f);
    const float INV_DELTA = (float)(TAB_D - 1) / TAB_MAX;
    int p = atomicAdd(&g_cursor[r], 1);
    g_ecol[p] = c;
    g_egeo[p] = make_float4(dx * inv, dy * inv, dz * inv, dist * INV_DELTA);
}

// ---------------- filter table build ----------------
#define TAB_SMEM_FLOATS 20736

extern "C" __global__ void __launch_bounds__(512, 1)
table_kernel(const float* __restrict__ fW1, const float* __restrict__ fb1,
             const float* __restrict__ fW2, const float* __restrict__ fb2) {
    extern __shared__ float sm[];
    float* hid = sm;
    float* rbf_s = sm + 8448;
    float* w1_s = sm + 9728;
    float* w2_s = sm + 8448;

    const int tid = threadIdx.x;
    const int layer = blockIdx.y;
    const int g0 = blockIdx.x * 64;
    const float* W1 = fW1 + layer * NRBF * HID;
    const float* b1 = fb1 + layer * HID;
    const float* W2 = fW2 + layer * HID * 3 * HID;
    const float* b2 = fb2 + layer * 3 * HID;
    const float DELTA = TAB_MAX / (float)(TAB_D - 1);

    for (int idx = tid; idx < 64 * NRBF; idx += 512) {
        int e = idx / NRBF, k = idx % NRBF;
        float d = (float)(g0 + e) * DELTA - RBF_STEP * (float)k;
        rbf_s[idx] = expf(-d * d);
    }
    for (int idx = tid; idx < NRBF * HID; idx += 512) w1_s[idx] = W1[idx];
    __syncthreads();

    const int jg = tid & 31;
    const int eg = tid >> 5;
    const int j0 = jg * 4;
    const int el0 = eg * 4;

    float hacc[4][4];
#pragma unroll
    for (int a = 0; a < 4; a++)
#pragma unroll
        for (int b = 0; b < 4; b++) hacc[a][b] = b1[j0 + b];
#pragma unroll
    for (int k = 0; k < NRBF; k++) {
        float r[4];
#pragma unroll
        for (int a = 0; a < 4; a++) r[a] = rbf_s[(el0 + a) * NRBF + k];
        float4 w = *(const float4*)&w1_s[k * HID + j0];
        float wv[4] = {w.x, w.y, w.z, w.w};
#pragma unroll
        for (int a = 0; a < 4; a++)
#pragma unroll
            for (int b = 0; b < 4; b++) hacc[a][b] += r[a] * wv[b];
    }
#pragma unroll
    for (int a = 0; a < 4; a++)
#pragma unroll
        for (int b = 0; b < 4; b++) hid[(el0 + a) * 132 + j0 + b] = silu_f(hacc[a][b]);
    __syncthreads();

    float a_ss[4][4], a_vv[4][4], a_sv[4][4];
#pragma unroll
    for (int a = 0; a < 4; a++)
#pragma unroll
        for (int b = 0; b < 4; b++) { a_ss[a][b] = 0.f; a_vv[a][b] = 0.f; a_sv[a][b] = 0.f; }

    for (int kc = 0; kc < HID; kc += 32) {
        __syncthreads();
        for (int idx = tid; idx < 32 * 384; idx += 512) w2_s[idx] = W2[kc * 384 + idx];
        __syncthreads();
#pragma unroll 8
        for (int kk = 0; kk < 32; kk++) {
            float h[4];
#pragma unroll
            for (int a = 0; a < 4; a++) h[a] = hid[(el0 + a) * 132 + kc + kk];
            float4 wss = *(const float4*)&w2_s[kk * 384 + j0];
            float4 wvv = *(const float4*)&w2_s[kk * 384 + 128 + j0];
            float4 wsv = *(const float4*)&w2_s[kk * 384 + 256 + j0];
            float ss[4] = {wss.x, wss.y, wss.z, wss.w};
            float vv[4] = {wvv.x, wvv.y, wvv.z, wvv.w};
            float sv[4] = {wsv.x, wsv.y, wsv.z, wsv.w};
#pragma unroll
            for (int a = 0; a < 4; a++)
#pragma unroll
                for (int b = 0; b < 4; b++) {
                    a_ss[a][b] += h[a] * ss[b];
                    a_vv[a][b] += h[a] * vv[b];
                    a_sv[a][b] += h[a] * sv[b];
                }
        }
    }

#pragma unroll
    for (int a = 0; a < 4; a++) {
        int gi = g0 + el0 + a;
        __half* Tx = (__half*)(g_htabh + ((size_t)layer * TAB_D + gi) * 384);
        __half* Ty = (__half*)(g_htabh + ((size_t)layer * TAB_D + gi - 1) * 384);
#pragma unroll
        for (int b = 0; b < 4; b++) {
            int ch = j0 + b;
            float hss = a_ss[a][b] + b2[ch];
            float hvv = a_vv[a][b] + b2[128 + ch];
            float hsv = a_sv[a][b] + b2[256 + ch];
            Tx[(0 * 128 + ch) * 2] = __float2half(hss);
            Tx[(1 * 128 + ch) * 2] = __float2half(hvv);
            Tx[(2 * 128 + ch) * 2] = __float2half(hsv);
            if (gi > 0) {
                Ty[(0 * 128 + ch) * 2 + 1] = __float2half(hss);
                Ty[(1 * 128 + ch) * 2 + 1] = __float2half(hvv);
                Ty[(2 * 128 + ch) * 2 + 1] = __float2half(hsv);
            }
        }
    }
}

// ---------------- edge message kernel ----------------
extern "C" __global__ void __launch_bounds__(256)
msg_kernel(int layer) {
    int r = (blockIdx.x * 256 + threadIdx.x) >> 5;
    int lane = threadIdx.x & 31;
    if (r >= N_ATOMS) return;

    int beg = g_rowptr[r];
    int end = g_rowptr[r + 1];
    int base = r * HID + lane * 4;

    if (beg >= end) {
        *(float4*)&g_ms[base] = make_float4(0.f, 0.f, 0.f, 0.f);
        *(float4*)&g_vn[base] = make_float4(0.f, 0.f, 0.f, 0.f);
        uint2 z; z.x = 0u; z.y = 0u;
        *(uint2*)&g_mvh[0 * NV + base] = z;
        *(uint2*)&g_mvh[1 * NV + base] = z;
        *(uint2*)&g_mvh[2 * NV + base] = z;
        return;
    }

    const bool hasv = (layer != 0);
    const __half2* Tl = g_htabh + (size_t)layer * TAB_D * 384;

    float accS[4] = {0.f, 0.f, 0.f, 0.f};
    float accV[12];
#pragma unroll
    for (int q = 0; q < 12; q++) accV[q] = 0.f;

    int colN = __ldg(&g_ecol[beg]);
    float4 geoN = __ldg(&g_egeo[beg]);
    float fN;
    const uint4* TbN;
    {
        float u = geoN.w;
        int i0 = (int)u;
        if (i0 > TAB_D - 2) i0 = TAB_D - 2;
        fN = fminf(u - (float)i0, 1.0f);
        TbN = (const uint4*)(Tl + (size_t)i0 * 384);
    }
    uint4 t0N = __ldcg(&TbN[lane]);
    uint4 t1N = __ldcg(&TbN[32 + lane]);
    uint4 t2N = __ldcg(&TbN[64 + lane]);
    uint2 sN = __ldcg((const uint2*)&g_sh[colN * HID + lane * 4]);
    uint2 v0N, v1N, v2N;
    v0N.x = v0N.y = v1N.x = v1N.y = v2N.x = v2N.y = 0u;
    if (hasv) {
        v0N = __ldcg((const uint2*)&g_vh[0 * NV + colN * HID + lane * 4]);
        v1N = __ldcg((const uint2*)&g_vh[1 * NV + colN * HID + lane * 4]);
        v2N = __ldcg((const uint2*)&g_vh[2 * NV + colN * HID + lane * 4]);
    }

    for (int p = beg; p < end; p++) {
        float4 geo = geoN;
        float f = fN;
        uint4 t0 = t0N, t1 = t1N, t2 = t2N;
        uint2 sv = sN, v0 = v0N, v1 = v1N, v2 = v2N;

        if (p + 1 < end) {
            colN = __ldg(&g_ecol[p + 1]);
            geoN = __ldg(&g_egeo[p + 1]);
            float u = geoN.w;
            int i0 = (int)u;
            if (i0 > TAB_D - 2) i0 = TAB_D - 2;
            fN = fminf(u - (float)i0, 1.0f);
            TbN = (const uint4*)(Tl + (size_t)i0 * 384);
            t0N = __ldcg(&TbN[lane]);
            t1N = __ldcg(&TbN[32 + lane]);
            t2N = __ldcg(&TbN[64 + lane]);
            sN = __ldcg((const uint2*)&g_sh[colN * HID + lane * 4]);
            if (hasv) {
                v0N = __ldcg((const uint2*)&g_vh[0 * NV + colN * HID + lane * 4]);
                v1N = __ldcg((const uint2*)&g_vh[1 * NV + colN * HID + lane * 4]);
                v2N = __ldcg((const uint2*)&g_vh[2 * NV + colN * HID + lane * 4]);
            }
        }

        float4 scf = h4_to_f4(sv);
        float sc[4] = {scf.x, scf.y, scf.z, scf.w};
        float vc0[4], vc1[4], vc2[4];
        if (hasv) {
            float4 a0 = h4_to_f4(v0);
            float4 a1 = h4_to_f4(v1);
            float4 a2 = h4_to_f4(v2);
            vc0[0] = a0.x; vc0[1] = a0.y; vc0[2] = a0.z; vc0[3] = a0.w;
            vc1[0] = a1.x; vc1[1] = a1.y; vc1[2] = a1.z; vc1[3] = a1.w;
            vc2[0] = a2.x; vc2[1] = a2.y; vc2[2] = a2.z; vc2[3] = a2.w;
        }

        const __half2* e0 = (const __half2*)&t0;
        const __half2* e1 = (const __half2*)&t1;
        const __half2* e2 = (const __half2*)&t2;
#pragma unroll
        for (int c = 0; c < 4; c++) {
            float2 pss = __half22float2(e0[c]);
            float2 pvv = __half22float2(e1[c]);
            float2 psv = __half22float2(e2[c]);
            float hss = pss.x + f * (pss.y - pss.x);
            float hvv = pvv.x + f * (pvv.y - pvv.x);
            float hsv = psv.x + f * (psv.y - psv.x);
            accS[c] += hss * sc[c];
            float cc = hsv * sc[c];
            if (hasv) {
                accV[c]     += hvv * vc0[c] + cc * geo.x;
                accV[4 + c] += hvv * vc1[c] + cc * geo.y;
                accV[8 + c] += hvv * vc2[c] + cc * geo.z;
            } else {
                accV[c]     += cc * geo.x;
                accV[4 + c] += cc * geo.y;
                accV[8 + c] += cc * geo.z;
            }
        }
    }

    *(float4*)&g_ms[base] = make_float4(accS[0], accS[1], accS[2], accS[3]);
    float vn[4];
#pragma unroll
    for (int c = 0; c < 4; c++)
        vn[c] = sqrtf(accV[c] * accV[c] + accV[4 + c] * accV[4 + c] + accV[8 + c] * accV[8 + c]);
    *(float4*)&g_vn[base] = make_float4(vn[0], vn[1], vn[2], vn[3]);
    *(uint2*)&g_mvh[0 * NV + base] = f4_to_h4(accV[0], accV[1], accV[2], accV[3]);
    *(uint2*)&g_mvh[1 * NV + base] = f4_to_h4(accV[4], accV[5], accV[6], accV[7]);
    *(uint2*)&g_mvh[2 * NV + base] = f4_to_h4(accV[8], accV[9], accV[10], accV[11]);
}

// ---------------- node update kernel (tf32 mma.sync) ----------------
// 64 nodes/CTA, 256 thr, 2 CTAs/SM. Warp (wn2 = w>>2: 32-node strip, wcq = w&3: 32-col strip).
// Each warp: 2 m16-tiles x 4 n8-tiles, fp32 accum, tf32 inputs (cvt at staging).
// smem floats: xs_t[64 k][76] @0 (4864) | wc[64 k][132] @4864 (8448) | ts_t[128 k][76] @13312 (9728)
#define NT 64
#define XS_STRIDE 76
#define WC_STRIDE 132
#define NODE_SMEM_FLOATS 23040

extern "C" __global__ void __launch_bounds__(256, 2)
node_kernel(int layer,
            const float* __restrict__ uW1, const float* __restrict__ ub1,
            const float* __restrict__ uW2, const float* __restrict__ ub2) {
    extern __shared__ float sm[];
    float* xs_t = sm;               // stage1 x tiles; alpha halves in stage2
    float* wc   = sm + 4864;        // weight chunk [64 k][132]
    float* ts_t = sm + 13312;       // t tiles [128 k][76]
    __half* alpha_s = (__half*)sm;  // [64 node][128 ch] halves (overlaps xs_t)

    const int tid = threadIdx.x;
    const int n0 = blockIdx.x * NT;
    const float* W1 = uW1 + layer * 384 * HID;
    const float* b1 = ub1 + layer * HID;
    const float* W2 = uW2 + layer * HID * 384;
    const float* b2 = ub2 + layer * 384;

    const int w = tid >> 5;
    const int lane = tid & 31;
    const int gid = lane >> 2;
    const int tig = lane & 3;
    const int wn2 = w >> 2;         // node strip: 32*wn2
    const int wcq = w & 3;          // col strip : 32*wcq
    const int nbase = 32 * wn2 + gid;
    const int cbase = 32 * wcq + gid;

    // xs staging mapping: thread -> (node, 4 k-quads)
    const int snode = tid & 63;
    const int sq = (tid >> 6) << 2;
    const int sgn = n0 + snode;
    const bool svalid = (sgn < N_ATOMS);

    float4 wreg[8];
#pragma unroll
    for (int q = 0; q < 8; q++) {
        int idx = q * 256 + tid;
        int k = idx >> 5, c4 = idx & 31;
        wreg[q] = *(const float4*)&W1[k * HID + c4 * 4];
    }

    float4 xpre[4];
    {
        const float* sp = g_s + (size_t)sgn * HID;
#pragma unroll
        for (int q = 0; q < 4; q++)
            xpre[q] = svalid ? *(const float4*)&sp[sq + 16 * q]
                             : make_float4(0.f, 0.f, 0.f, 0.f);
    }

    // ---- stage 1: T = silu(X @ W1 + b1) ----
    float c1r[2][4][4];
#pragma unroll
    for (int nt = 0; nt < 4; nt++) {
        int cl = 32 * wcq + 8 * nt + 2 * tig;
        float bb0 = b1[cl], bb1 = b1[cl + 1];
#pragma unroll
        for (int mt = 0; mt < 2; mt++) {
            c1r[mt][nt][0] = bb0; c1r[mt][nt][1] = bb1;
            c1r[mt][nt][2] = bb0; c1r[mt][nt][3] = bb1;
        }
    }

    for (int kc = 0; kc < 384; kc += 64) {
        __syncthreads();
#pragma unroll
        for (int q = 0; q < 8; q++) {
            int idx = q * 256 + tid;
            int k = idx >> 5, c4 = idx & 31;
            *(float4*)&wc[k * WC_STRIDE + c4 * 4] =
                make_float4(tf32f(wreg[q].x), tf32f(wreg[q].y),
                            tf32f(wreg[q].z), tf32f(wreg[q].w));
        }
#pragma unroll
        for (int q = 0; q < 4; q++) {
            int kl = sq + 16 * q;
            xs_t[(kl + 0) * XS_STRIDE + snode] = tf32f(xpre[q].x);
            xs_t[(kl + 1) * XS_STRIDE + snode] = tf32f(xpre[q].y);
            xs_t[(kl + 2) * XS_STRIDE + snode] = tf32f(xpre[q].z);
            xs_t[(kl + 3) * XS_STRIDE + snode] = tf32f(xpre[q].w);
        }
        __syncthreads();
        if (kc + 64 < 384) {
            int nkc = kc + 64;
            const float* src = (nkc < 128) ? g_s : ((nkc < 256) ? g_ms : g_vn);
            const float* sp = src + (size_t)sgn * HID + (nkc & 127);
#pragma unroll
            for (int q = 0; q < 8; q++) {
                int idx = q * 256 + tid;
                int k = idx >> 5, c4 = idx & 31;
                wreg[q] = *(const float4*)&W1[(nkc + k) * HID + c4 * 4];
            }
#pragma unroll
            for (int q = 0; q < 4; q++)
                xpre[q] = svalid ? *(const float4*)&sp[sq + 16 * q]
                                 : make_float4(0.f, 0.f, 0.f, 0.f);
        } else {
#pragma unroll
            for (int q = 0; q < 8; q++) {
                int idx = q * 256 + tid;
                int k = idx >> 5, c4 = idx & 31;
                wreg[q] = *(const float4*)&W2[k * 384 + c4 * 4];
            }
        }
#pragma unroll
        for (int kk8 = 0; kk8 < 8; kk8++) {
            int kb = kk8 * 8;
            const float* xr0 = &xs_t[(kb + tig) * XS_STRIDE];
            const float* xr1 = &xs_t[(kb + tig + 4) * XS_STRIDE];
            uint a[2][4];
#pragma unroll
            for (int mt = 0; mt < 2; mt++) {
                int nb = nbase + 16 * mt;
                a[mt][0] = __float_as_uint(xr0[nb]);
                a[mt][1] = __float_as_uint(xr0[nb + 8]);
                a[mt][2] = __float_as_uint(xr1[nb]);
                a[mt][3] = __float_as_uint(xr1[nb + 8]);
            }
            const float* wr0 = &wc[(kb + tig) * WC_STRIDE];
            const float* wr1 = &wc[(kb + tig + 4) * WC_STRIDE];
#pragma unroll
            for (int nt = 0; nt < 4; nt++) {
                uint b0 = __float_as_uint(wr0[cbase + 8 * nt]);
                uint b1u = __float_as_uint(wr1[cbase + 8 * nt]);
                mma_tf32(c1r[0][nt], a[0][0], a[0][1], a[0][2], a[0][3], b0, b1u);
                mma_tf32(c1r[1][nt], a[1][0], a[1][1], a[1][2], a[1][3], b0, b1u);
            }
        }
    }

    // silu + write ts_t (k-major, tf32)
#pragma unroll
    for (int mt = 0; mt < 2; mt++) {
        int lr = 32 * wn2 + 16 * mt + gid;
#pragma unroll
        for (int nt = 0; nt < 4; nt++) {
            int cl = 32 * wcq + 8 * nt + 2 * tig;
            ts_t[(cl + 0) * XS_STRIDE + lr]     = tf32f(silu_f(c1r[mt][nt][0]));
            ts_t[(cl + 1) * XS_STRIDE + lr]     = tf32f(silu_f(c1r[mt][nt][1]));
            ts_t[(cl + 0) * XS_STRIDE + lr + 8] = tf32f(silu_f(c1r[mt][nt][2]));
            ts_t[(cl + 1) * XS_STRIDE + lr + 8] = tf32f(silu_f(c1r[mt][nt][3]));
        }
    }

    // ---- stage 2: U = T @ W2 + b2 ----
    float u2r[2][4][4];
    for (int c = 0; c < 6; c++) {
        int jb = c >> 1;
        int kc2 = (c & 1) * 64;
        if (kc2 == 0) {
#pragma unroll
            for (int mt = 0; mt < 2; mt++)
#pragma unroll
                for (int nt = 0; nt < 4; nt++)
#pragma unroll
                    for (int x = 0; x < 4; x++) u2r[mt][nt][x] = 0.f;
        }
        __syncthreads();
#pragma unroll
        for (int q = 0; q < 8; q++) {
            int idx = q * 256 + tid;
            int k = idx >> 5, c4 = idx & 31;
            *(float4*)&wc[k * WC_STRIDE + c4 * 4] =
                make_float4(tf32f(wreg[q].x), tf32f(wreg[q].y),
                            tf32f(wreg[q].z), tf32f(wreg[q].w));
        }
        __syncthreads();
        if (c < 5) {
            int cn = c + 1;
            int jbn = cn >> 1;
            int kc2n = (cn & 1) * 64;
#pragma unroll
            for (int q = 0; q < 8; q++) {
                int idx = q * 256 + tid;
                int k = idx >> 5, c4 = idx & 31;
                wreg[q] = *(const float4*)&W2[(kc2n + k) * 384 + jbn * 128 + c4 * 4];
            }
        }
#pragma unroll
        for (int kk8 = 0; kk8 < 8; kk8++) {
            int kb = kk8 * 8;
            const float* tr0 = &ts_t[(kc2 + kb + tig) * XS_STRIDE];
            const float* tr1 = &ts_t[(kc2 + kb + tig + 4) * XS_STRIDE];
            uint a[2][4];
#pragma unroll
            for (int mt = 0; mt < 2; mt++) {
                int nb = nbase + 16 * mt;
                a[mt][0] = __float_as_uint(tr0[nb]);
                a[mt][1] = __float_as_uint(tr0[nb + 8]);
                a[mt][2] = __float_as_uint(tr1[nb]);
                a[mt][3] = __float_as_uint(tr1[nb + 8]);
            }
            const float* wr0 = &wc[(kb + tig) * WC_STRIDE];
            const float* wr1 = &wc[(kb + tig + 4) * WC_STRIDE];
#pragma unroll
            for (int nt = 0; nt < 4; nt++) {
                uint b0 = __float_as_uint(wr0[cbase + 8 * nt]);
                uint b1u = __float_as_uint(wr1[cbase + 8 * nt]);
                mma_tf32(u2r[0][nt], a[0][0], a[0][1], a[0][2], a[0][3], b0, b1u);
                mma_tf32(u2r[1][nt], a[1][0], a[1][1], a[1][2], a[1][3], b0, b1u);
            }
        }

        if (kc2 == 64) {
#pragma unroll
            for (int mt = 0; mt < 2; mt++) {
#pragma unroll
                for (int rs = 0; rs < 2; rs++) {
                    int lr = 32 * wn2 + 16 * mt + gid + rs * 8;
                    int gn = n0 + lr;
                    if (gn >= N_ATOMS) continue;
#pragma unroll
                    for (int nt = 0; nt < 4; nt++) {
                        int j = 32 * wcq + 8 * nt + 2 * tig;
                        float u0 = u2r[mt][nt][rs * 2 + 0] + b2[jb * 128 + j];
                        float u1 = u2r[mt][nt][rs * 2 + 1] + b2[jb * 128 + j + 1];
                        if (jb == 0) {
                            float2* sp = (float2*)&g_s[gn * HID + j];
                            float2 s = *sp;
                            s.x += u0; s.y += u1;
                            *sp = s;
                            *(__half2*)&g_sh[gn * HID + j] = __floats2half2_rn(s.x, s.y);
                        } else if (jb == 1) {
                            *(__half2*)&alpha_s[lr * HID + j] = __floats2half2_rn(u0, u1);
                        } else {
                            float2 al = __half22float2(*(__half2*)&alpha_s[lr * HID + j]);
#pragma unroll
                            for (int d = 0; d < 3; d++) {
                                float2 mv = __half22float2(*(__half2*)&g_mvh[d * NV + gn * HID + j]);
                                float2 vo = make_float2(0.f, 0.f);
                                if (layer != 0)
                                    vo = __half22float2(*(__half2*)&g_vh[d * NV + gn * HID + j]);
                                float nx = al.x * vo.x + u0 * mv.x;
                                float ny = al.y * vo.y + u1 * mv.y;
                                *(__half2*)&g_vh[d * NV + gn * HID + j] = __floats2half2_rn(nx, ny);
                            }
                        }
                    }
                }
            }
        }
    }
}

// ---------------- molecule pooling + heads ----------------
__global__ void pool_zero_kernel() {
    int idx = blockIdx.x * blockDim.x + threadIdx.x;
    if (idx < N_MOLS * HID) g_hmol[idx] = 0.f;
    if (idx < N_MOLS) g_cnt[idx] = 0.f;
}

__global__ void pool_acc_kernel(const int* __restrict__ batch) {
    int idx = blockIdx.x * blockDim.x + threadIdx.x;
    if (idx >= NV) return;
    int n = idx >> 7;
    int j = idx & 127;
    int m = batch[n];
    atomicAdd(&g_hmol[m * HID + j], g_s[idx]);
    if (j == 0) atomicAdd(&g_cnt[m], 1.0f);
}

__global__ void head_kernel(const float* __restrict__ lW1, const float* __restrict__ lb1,
                            const float* __restrict__ lW2, const float* __restrict__ lb2,
                            const float* __restrict__ pW1, const float* __restrict__ pb1,
                            const float* __restrict__ pW2, const float* __restrict__ pb2,
                            float* __restrict__ out) {
    __shared__ float hm[HID];
    __shared__ float tt[HID];
    __shared__ float red[HID];
    int m = blockIdx.x;
    int j = threadIdx.x;
    float cnt = g_cnt[m];
    hm[j] = g_hmol[m * HID + j] / cnt;
    __syncthreads();

    float acc = lb1[j];
    for (int k = 0; k < HID; k++) acc += hm[k] * lW1[k * HID + j];
    tt[j] = silu_f(acc);
    __syncthreads();
    red[j] = tt[j] * lW2[j];
    __syncthreads();
    for (int s = 64; s > 0; s >>= 1) {
        if (j < s) red[j] += red[j + s];
        __syncthreads();
    }
    if (j == 0) out[m] = red[0] + lb2[0];
    __syncthreads();

    acc = pb1[j];
    for (int k = 0; k < HID; k++) acc += hm[k] * pW1[k * HID + j];
    tt[j] = silu_f(acc);
    __syncthreads();
    red[j] = tt[j] * pW2[j];
    __syncthreads();
    for (int s = 64; s > 0; s >>= 1) {
        if (j < s) red[j] += red[j + s];
        __syncthreads();
    }
    if (j == 0) {
        float x = red[0] + pb2[0];
        out[N_MOLS + m] = 1.0f / (1.0f + expf(-x));
    }
}

// ---------------- launch ----------------
extern "C" void kernel_launch(void* const* d_in, const int* in_sizes, int n_in,
                              void* d_out, int out_size) {
    const int* z = (const int*)d_in[0];
    const float* pos = (const float*)d_in[1];
    const int* ei = (const int*)d_in[2];
    const int* batch = (const int*)d_in[3];
    const float* emb = (const float*)d_in[4];
    const float* fW1 = (const float*)d_in[5];
    const float* fb1 = (const float*)d_in[6];
    const float* fW2 = (const float*)d_in[7];
    const float* fb2 = (const float*)d_in[8];
    const float* uW1 = (const float*)d_in[9];
    const float* ub1 = (const float*)d_in[10];
    const float* uW2 = (const float*)d_in[11];
    const float* ub2 = (const float*)d_in[12];
    const float* lW1 = (const float*)d_in[13];
    const float* lb1 = (const float*)d_in[14];
    const float* lW2 = (const float*)d_in[15];
    const float* lb2 = (const float*)d_in[16];
    const float* pW1 = (const float*)d_in[17];
    const float* pb1 = (const float*)d_in[18];
    const float* pW2 = (const float*)d_in[19];
    const float* pb2 = (const float*)d_in[20];
    float* out = (float*)d_out;

    cudaFuncSetAttribute(table_kernel, cudaFuncAttributeMaxDynamicSharedMemorySize,
                         TAB_SMEM_FLOATS * 4);
    cudaFuncSetAttribute(node_kernel, cudaFuncAttributeMaxDynamicSharedMemorySize,
                         NODE_SMEM_FLOATS * 4);

    init_kernel<<<(NV + 255) / 256, 256>>>(z, emb);

    const int scan_blocks = (N_ATOMS + SCAN_B - 1) / SCAN_B;
    hist_kernel<<<(N_EDGES + 255) / 256, 256>>>(ei);
    scan1_kernel<<<scan_blocks, SCAN_B>>>();
    scan2_kernel<<<1, 32>>>(scan_blocks);
    scan3_kernel<<<(N_ATOMS + 255) / 256, 256>>>();
    scatter_kernel<<<(N_EDGES + 255) / 256, 256>>>(ei, pos);

    table_kernel<<<dim3(TAB_D / 64, NLAYERS), 512, TAB_SMEM_FLOATS * 4>>>(fW1, fb1, fW2, fb2);

    const int msg_blocks = (N_ATOMS * 32 + 255) / 256;
    const int node_blocks = (N_ATOMS + NT - 1) / NT;
    for (int layer = 0; layer < NLAYERS; layer++) {
        msg_kernel<<<msg_blocks, 256>>>(layer);
        node_kernel<<<node_blocks, 256, NODE_SMEM_FLOATS * 4>>>(layer, uW1, ub1, uW2, ub2);
    }

    pool_zero_kernel<<<(N_MOLS * HID + 255) / 256, 256>>>();
    pool_acc_kernel<<<(NV + 255) / 256, 256>>>(batch);
    head_kernel<<<N_MOLS, HID>>>(lW1, lb1, lW2, lb2, pW1, pb1, pW2, pb2, out);
}